// round 9
// baseline (speedup 1.0000x reference)
#include <cuda_runtime.h>
#include <cuda_fp16.h>
#include <math.h>

#define WSZ 11

// Gaussian weights (sigma=1.5, ws=11) as compile-time constants -> FFMA-imm
__device__ constexpr float CWA[WSZ] = {
    0.00102838f, 0.00759875f, 0.03600080f, 0.10936069f, 0.21300554f,
    0.26601173f, 0.21300554f, 0.10936069f, 0.03600080f, 0.00759875f,
    0.00102838f};

// packed (w,w) f32x2 weight constants
constexpr unsigned long long WPK(float f) {
    unsigned u = __builtin_bit_cast(unsigned int, f);
    return ((unsigned long long)u << 32) | u;
}
__device__ constexpr unsigned long long CWP[WSZ] = {
    WPK(0.00102838f), WPK(0.00759875f), WPK(0.03600080f), WPK(0.10936069f),
    WPK(0.21300554f), WPK(0.26601173f), WPK(0.21300554f), WPK(0.10936069f),
    WPK(0.03600080f), WPK(0.00759875f), WPK(0.00102838f)};

// ---- packed f32x2 helpers ---------------------------------------------------
__device__ __forceinline__ unsigned long long packf2(float lo, float hi) {
    unsigned long long r;
    asm("mov.b64 %0, {%1, %2};" : "=l"(r) : "f"(lo), "f"(hi));
    return r;
}
__device__ __forceinline__ float2 unpackf2(unsigned long long v) {
    float lo, hi;
    asm("mov.b64 {%0, %1}, %2;" : "=f"(lo), "=f"(hi) : "l"(v));
    return make_float2(lo, hi);
}
__device__ __forceinline__ void fma2(unsigned long long& d,
                                     unsigned long long a,
                                     unsigned long long b) {
    asm("fma.rn.f32x2 %0, %1, %2, %0;" : "+l"(d) : "l"(a), "l"(b));
}

// ---------------- static device state (no allocations allowed) --------------
__device__ double g_ssim_sum[5];
__device__ double g_cs_sum[5];
__device__ int    g_fmax[5];
__device__ int    g_fmin[5];

// intermediates stored as fp16 (compute stays fp32)
__device__ __half g_s1[67829760];  // [5][2][S][S][WP]   level0
__device__ __half g_s2[64289280];  // [5][2][S][Ho][WP]  level0
// pooled pyramids (levels 1..4), fp32
__device__ float g_p1[2021760];
__device__ float g_p2[2021760];

static const long h_off[5] = {0, 0, 1769472, 1990656, 2018304};

// ---- half4 <-> float4 helpers ----------------------------------------------
__device__ __forceinline__ uint2 f4_to_h4(float4 v) {
    __half2 lo = __floats2half2_rn(v.x, v.y);
    __half2 hi = __floats2half2_rn(v.z, v.w);
    uint2 r;
    r.x = *(unsigned*)&lo;
    r.y = *(unsigned*)&hi;
    return r;
}

// ---------------------------------------------------------------------------
__global__ void k_init() {
    int t = threadIdx.x;
    if (t < 5) {
        g_ssim_sum[t] = 0.0;
        g_cs_sum[t]   = 0.0;
        g_fmax[t]     = 0;
        g_fmin[t]     = 0;
    }
}

// ------------- pass 1: W-conv + fused 2x2x2 avg-pool + flags ----------------
template <int S>
__global__ void k_pass1(const float* __restrict__ i1_0,
                        const float* __restrict__ i2_0, int lvl,
                        long poff_in, long poff_out) {
    constexpr int  Wo  = S - 10;
    constexpr int  WP  = (Wo + 3) & ~3;
    constexpr int  WP4 = WP / 4;
    constexpr int  SP  = S + 8;
    constexpr int  T   = S / 2;
    constexpr int  BT  = (4 * WP4 < 64) ? 64 : 4 * WP4;
    constexpr long FSZ = 2L * S * S * WP;

    __shared__ float s1[4 * SP];
    __shared__ float s2[4 * SP];
    __shared__ int   sfl;

    const float* i1 = (lvl == 0) ? i1_0 : (g_p1 + poff_in);
    const float* i2 = (lvl == 0) ? i2_0 : (g_p2 + poff_in);

    const int tid = threadIdx.x;
    int bid = blockIdx.x;
    int hp  = bid % (S / 2);
    int t0  = bid / (S / 2);
    int dp  = t0 % (S / 2);
    int b   = t0 / (S / 2);
    if (tid == 0) sfl = 0;

    bool mx = false, mn = false;
    for (int idx = tid; idx < 4 * SP; idx += BT) {
        int r  = idx / SP, ii = idx - r * SP;
        int d  = 2 * dp + (r >> 1);
        int h  = 2 * hp + (r & 1);
        float v1 = 0.f, v2 = 0.f;
        if (ii < S) {
            long gb = (((long)b * S + d) * S + h) * S + ii;
            v1 = i1[gb];
            v2 = i2[gb];
        }
        s1[idx] = v1;
        s2[idx] = v2;
        mx |= (v1 > 128.0f);
        mn |= (v1 < -0.5f);
    }
    __syncthreads();
    if (mx | mn) atomicOr(&sfl, (mx ? 1 : 0) | (mn ? 2 : 0));

    for (int task = tid; task < 4 * WP4; task += BT) {
        int r = task / WP4, q = task - r * WP4;
        int d = 2 * dp + (r >> 1);
        int h = 2 * hp + (r & 1);
        float xs[16], ys[16];
        {
            const float4* p1 = (const float4*)&s1[r * SP + 4 * q];
            const float4* p2 = (const float4*)&s2[r * SP + 4 * q];
#pragma unroll
            for (int m = 0; m < 4; m++) {
                float4 a = p1[m], bb = p2[m];
                xs[4 * m] = a.x;  xs[4 * m + 1] = a.y;  xs[4 * m + 2] = a.z;  xs[4 * m + 3] = a.w;
                ys[4 * m] = bb.x; ys[4 * m + 1] = bb.y; ys[4 * m + 2] = bb.z; ys[4 * m + 3] = bb.w;
            }
        }
        float xx[14], yy[14], xy[14];
#pragma unroll
        for (int m = 0; m < 14; m++) {
            xx[m] = xs[m] * xs[m];
            yy[m] = ys[m] * ys[m];
            xy[m] = xs[m] * ys[m];
        }
        float a1[4] = {0, 0, 0, 0}, a2[4] = {0, 0, 0, 0}, b1[4] = {0, 0, 0, 0},
              b2[4] = {0, 0, 0, 0}, b3[4] = {0, 0, 0, 0};
#pragma unroll
        for (int k = 0; k < WSZ; k++) {
            const float w = CWA[k];
#pragma unroll
            for (int j = 0; j < 4; j++) {
                a1[j] = fmaf(w, xs[k + j], a1[j]);
                a2[j] = fmaf(w, ys[k + j], a2[j]);
                b1[j] = fmaf(w, xx[k + j], b1[j]);
                b2[j] = fmaf(w, yy[k + j], b2[j]);
                b3[j] = fmaf(w, xy[k + j], b3[j]);
            }
        }
        long grow = ((long)b * S + d) * S + h;
        long o    = grow * WP + 4 * q;
        *(uint2*)&g_s1[o]           = f4_to_h4(make_float4(a1[0], a1[1], a1[2], a1[3]));
        *(uint2*)&g_s1[FSZ + o]     = f4_to_h4(make_float4(a2[0], a2[1], a2[2], a2[3]));
        *(uint2*)&g_s1[2 * FSZ + o] = f4_to_h4(make_float4(b1[0], b1[1], b1[2], b1[3]));
        *(uint2*)&g_s1[3 * FSZ + o] = f4_to_h4(make_float4(b2[0], b2[1], b2[2], b2[3]));
        *(uint2*)&g_s1[4 * FSZ + o] = f4_to_h4(make_float4(b3[0], b3[1], b3[2], b3[3]));
    }

    if (lvl < 4) {
        float* o1 = g_p1 + poff_out;
        float* o2 = g_p2 + poff_out;
        long orow = (((long)b * T + dp) * T + hp) * T;
        for (int x = tid; x < T; x += BT) {
            float r1 = 0.f, r2 = 0.f;
#pragma unroll
            for (int r = 0; r < 4; r++) {
                r1 += s1[r * SP + 2 * x] + s1[r * SP + 2 * x + 1];
                r2 += s2[r * SP + 2 * x] + s2[r * SP + 2 * x + 1];
            }
            o1[orow + x] = r1 * 0.125f;
            o2[orow + x] = r2 * 0.125f;
        }
    }

    __syncthreads();
    if (tid == 0 && sfl) {
        if ((sfl & 1) && !g_fmax[lvl]) atomicOr(&g_fmax[lvl], 1);
        if ((sfl & 2) && !g_fmin[lvl]) atomicOr(&g_fmin[lvl], 1);
    }
}

// ------------- pass 2: H-conv, half4 loads, f32x2 packed FMA ----------------
template <int S>
__global__ void k_pass2() {
    constexpr int Wo = S - 10, Ho = S - 10;
    constexpr int WP  = (Wo + 3) & ~3;
    constexpr int NQ  = WP / 4;
    constexpr int TH  = 12;
    constexpr int NHT = (Ho + TH - 1) / TH;
    constexpr int TOT = 10 * S * NHT * NQ;

    int idx = blockIdx.x * blockDim.x + threadIdx.x;
    if (idx >= TOT) return;
    int quad = idx % NQ;
    int t    = idx / NQ;
    int ht   = t % NHT;
    int q    = t / NHT;
    int ho0  = ht * TH;

    const __half* in = g_s1 + (long)q * S * WP + quad * 4;
    unsigned long long accA[TH], accB[TH];
#pragma unroll
    for (int j = 0; j < TH; j++) { accA[j] = 0ull; accB[j] = 0ull; }

#pragma unroll
    for (int k = 0; k < TH + 10; k++) {
        int h = ho0 + k;
        if (h < S) {
            uint2 u = *(const uint2*)(in + (long)h * WP);
            float2 lo = __half22float2(*(__half2*)&u.x);
            float2 hi = __half22float2(*(__half2*)&u.y);
            unsigned long long vA = packf2(lo.x, lo.y);
            unsigned long long vB = packf2(hi.x, hi.y);
#pragma unroll
            for (int j = 0; j < TH; j++) {
                int tt = k - j;
                if (tt >= 0 && tt < WSZ) {
                    fma2(accA[j], CWP[tt], vA);
                    fma2(accB[j], CWP[tt], vB);
                }
            }
        }
    }
    __half* out = g_s2 + (long)q * Ho * WP + quad * 4;
#pragma unroll
    for (int j = 0; j < TH; j++) {
        int ho = ho0 + j;
        if (ho < Ho) {
            float2 a = unpackf2(accA[j]);
            float2 b = unpackf2(accB[j]);
            *(uint2*)(out + (long)ho * WP) =
                f4_to_h4(make_float4(a.x, a.y, b.x, b.y));
        }
    }
}

// ------------- pass 3: D-conv + SSIM/CS + reduction, f32x2 packed FMA -------
__device__ __forceinline__ float warp_sum(float v) {
#pragma unroll
    for (int o = 16; o; o >>= 1) v += __shfl_down_sync(0xffffffffu, v, o);
    return v;
}

template <int S>
__global__ void k_pass3(int lvl) {
    constexpr int  Wo  = S - 10, Ho = Wo, Do = Wo;
    constexpr int  WP  = (Wo + 3) & ~3;
    constexpr int  NQ2 = WP / 2;
    constexpr int  TD  = 6;
    constexpr int  NDT = (Do + TD - 1) / TD;
    constexpr long HWP = (long)Ho * WP;
    constexpr long FST = 2L * S * HWP;
    constexpr int  TOT = 2 * NDT * Ho * NQ2;

    int idx = blockIdx.x * blockDim.x + threadIdx.x;
    float sum_s = 0.f, sum_c = 0.f;
    if (idx < TOT) {
        int p  = idx % NQ2;
        int t  = idx / NQ2;
        int ho = t % Ho;
        int t2 = t / Ho;
        int dt = t2 % NDT;
        int b  = t2 / NDT;
        int d0 = dt * TD;

        const __half* base = g_s2 + (long)b * S * HWP + (long)ho * WP + 2 * p;
        unsigned long long A0[TD], A1[TD], A2[TD], A3[TD], A4[TD];
#pragma unroll
        for (int j = 0; j < TD; j++) {
            A0[j] = A1[j] = A2[j] = A3[j] = A4[j] = 0ull;
        }
#pragma unroll
        for (int k = 0; k < TD + 10; k++) {
            int d = d0 + k;
            if (d < S) {
                const __half* pp = base + (long)d * HWP;
                float2 f0 = __half22float2(*(const __half2*)(pp));
                float2 f1 = __half22float2(*(const __half2*)(pp + FST));
                float2 f2 = __half22float2(*(const __half2*)(pp + 2 * FST));
                float2 f3 = __half22float2(*(const __half2*)(pp + 3 * FST));
                float2 f4 = __half22float2(*(const __half2*)(pp + 4 * FST));
                unsigned long long v0 = packf2(f0.x, f0.y);
                unsigned long long v1 = packf2(f1.x, f1.y);
                unsigned long long v2 = packf2(f2.x, f2.y);
                unsigned long long v3 = packf2(f3.x, f3.y);
                unsigned long long v4 = packf2(f4.x, f4.y);
#pragma unroll
                for (int j = 0; j < TD; j++) {
                    int tt = k - j;
                    if (tt >= 0 && tt < WSZ) {
                        fma2(A0[j], CWP[tt], v0);
                        fma2(A1[j], CWP[tt], v1);
                        fma2(A2[j], CWP[tt], v2);
                        fma2(A3[j], CWP[tt], v3);
                        fma2(A4[j], CWP[tt], v4);
                    }
                }
            }
        }
        float maxv = g_fmax[lvl] ? 255.0f : 1.0f;
        float minv = g_fmin[lvl] ? -1.0f : 0.0f;
        float L  = maxv - minv;
        float C1 = (0.01f * L) * (0.01f * L);
        float C2 = (0.03f * L) * (0.03f * L);
        bool lane0 = (2 * p) < Wo;
        bool lane1 = (2 * p + 1) < Wo;
#pragma unroll
        for (int j = 0; j < TD; j++) {
            if (d0 + j < Do) {
                float2 m1 = unpackf2(A0[j]);
                float2 m2 = unpackf2(A1[j]);
                float2 q1 = unpackf2(A2[j]);
                float2 q2 = unpackf2(A3[j]);
                float2 q3 = unpackf2(A4[j]);
                if (lane0) {
                    float mu1 = m1.x, mu2 = m2.x;
                    float v1 = 2.0f * (q3.x - mu1 * mu2) + C2;
                    float v2 = (q1.x - mu1 * mu1) + (q2.x - mu2 * mu2) + C2;
                    sum_c += v1 / v2;
                    sum_s += (2.0f * mu1 * mu2 + C1) * v1 /
                             ((mu1 * mu1 + mu2 * mu2 + C1) * v2);
                }
                if (lane1) {
                    float mu1 = m1.y, mu2 = m2.y;
                    float v1 = 2.0f * (q3.y - mu1 * mu2) + C2;
                    float v2 = (q1.y - mu1 * mu1) + (q2.y - mu2 * mu2) + C2;
                    sum_c += v1 / v2;
                    sum_s += (2.0f * mu1 * mu2 + C1) * v1 /
                             ((mu1 * mu1 + mu2 * mu2 + C1) * v2);
                }
            }
        }
    }
    sum_c = warp_sum(sum_c);
    sum_s = warp_sum(sum_s);
    __shared__ float shc[4], shs[4];
    int lane = threadIdx.x & 31, wid = threadIdx.x >> 5;
    if (lane == 0) { shc[wid] = sum_c; shs[wid] = sum_s; }
    __syncthreads();
    if (threadIdx.x == 0) {
        float tc = shc[0] + shc[1] + shc[2] + shc[3];
        float ts = shs[0] + shs[1] + shs[2] + shs[3];
        atomicAdd(&g_cs_sum[lvl],   (double)tc);
        atomicAdd(&g_ssim_sum[lvl], (double)ts);
    }
}

// ------------- final combine -------------------------------------------------
__global__ void k_final(float* out) {
    const double W[5]   = {0.0448, 0.2856, 0.3001, 0.2363, 0.1333};
    const double cnt[5] = {12057136.0, 1272112.0, 109744.0, 5488.0, 16.0};
    double p = 1.0;
    for (int l = 0; l < 4; l++) p *= pow(g_cs_sum[l] / cnt[l], W[l]);
    p *= pow(g_ssim_sum[4] / cnt[4], W[4]);
    out[0] = (float)p;
}

// ---------------------------------------------------------------------------
template <int S>
static void run_level(const float* i1, const float* i2, int lvl,
                      long poff_in, long poff_out) {
    constexpr int Wo  = S - 10;
    constexpr int WP  = (Wo + 3) & ~3;
    constexpr int WP4 = WP / 4;
    constexpr int BT  = (4 * WP4 < 64) ? 64 : 4 * WP4;
    int nblk = 2 * (S / 2) * (S / 2);
    k_pass1<S><<<nblk, BT>>>(i1, i2, lvl, poff_in, poff_out);

    constexpr int TH = 12, NHT = (Wo + TH - 1) / TH, NQ = WP / 4;
    int tot2 = 10 * S * NHT * NQ;
    k_pass2<S><<<(tot2 + 127) / 128, 128>>>();

    constexpr int TD = 6, NDT = (Wo + TD - 1) / TD, NQ2 = WP / 2;
    int tot3 = 2 * NDT * Wo * NQ2;
    k_pass3<S><<<(tot3 + 127) / 128, 128>>>(lvl);
}

extern "C" void kernel_launch(void* const* d_in, const int* in_sizes, int n_in,
                              void* d_out, int out_size) {
    const float* img1 = (const float*)d_in[0];
    const float* img2 = (const float*)d_in[1];

    k_init<<<1, 32>>>();
    run_level<192>(img1, img2, 0, 0,        h_off[1]);
    run_level<96>(img1, img2, 1, h_off[1], h_off[2]);
    run_level<48 >(img1, img2, 2, h_off[2], h_off[3]);
    run_level<24 >(img1, img2, 3, h_off[3], h_off[4]);
    run_level<12 >(img1, img2, 4, h_off[4], 0);
    k_final<<<1, 1>>>((float*)d_out);
}

// round 11
// speedup vs baseline: 1.1584x; 1.1584x over previous
#include <cuda_runtime.h>
#include <cuda_fp16.h>
#include <math.h>

#define WSZ 11

// Gaussian weights (sigma=1.5, ws=11), fp32 exact
__device__ constexpr float CWA[WSZ] = {
    0.00102838f, 0.00759875f, 0.03600080f, 0.10936069f, 0.21300554f,
    0.26601173f, 0.21300554f, 0.10936069f, 0.03600080f, 0.00759875f,
    0.00102838f};

// ---- compile-time float<->half converters ----------------------------------
constexpr unsigned short F2H(float f) {
    unsigned u = __builtin_bit_cast(unsigned int, f);
    unsigned sign = (u >> 16) & 0x8000u;
    int exp = (int)((u >> 23) & 0xffu) - 127 + 15;
    unsigned man = u & 0x7fffffu;
    unsigned base = ((unsigned)exp << 10) | (man >> 13);
    unsigned rem = man & 0x1fffu;
    if (rem > 0x1000u || (rem == 0x1000u && (base & 1u))) base++;
    return (unsigned short)(sign | base);
}
constexpr float H2F(unsigned short h) {
    int e = (h >> 10) & 31;
    unsigned m = h & 1023u;
    float f = 1.0f + (float)m / 1024.0f;
    int k = e - 15;
    while (k > 0) { f *= 2.0f; k--; }
    while (k < 0) { f *= 0.5f; k++; }
    return f;
}
constexpr unsigned HSPLAT(float f) {
    unsigned short h = F2H(f);
    return ((unsigned)h << 16) | h;
}
// exact sum of half-rounded weights
constexpr float SHSUM() {
    float s = 0.f;
    for (int i = 0; i < WSZ; i++) s += H2F(F2H(CWA[i]));
    return s;
}
// pass1 fp32 weights renormalized so (pass1)*(half pass2)*(half pass3) sums to 1
__device__ constexpr float CW1[WSZ] = {
    CWA[0] / (SHSUM() * SHSUM()), CWA[1] / (SHSUM() * SHSUM()),
    CWA[2] / (SHSUM() * SHSUM()), CWA[3] / (SHSUM() * SHSUM()),
    CWA[4] / (SHSUM() * SHSUM()), CWA[5] / (SHSUM() * SHSUM()),
    CWA[6] / (SHSUM() * SHSUM()), CWA[7] / (SHSUM() * SHSUM()),
    CWA[8] / (SHSUM() * SHSUM()), CWA[9] / (SHSUM() * SHSUM()),
    CWA[10] / (SHSUM() * SHSUM())};
// half2-splat weights for pass2/pass3
__device__ constexpr unsigned CWH[WSZ] = {
    HSPLAT(CWA[0]), HSPLAT(CWA[1]), HSPLAT(CWA[2]), HSPLAT(CWA[3]),
    HSPLAT(CWA[4]), HSPLAT(CWA[5]), HSPLAT(CWA[6]), HSPLAT(CWA[7]),
    HSPLAT(CWA[8]), HSPLAT(CWA[9]), HSPLAT(CWA[10])};

__device__ __forceinline__ __half2 u2h2(unsigned u) {
    return *(__half2*)&u;
}

// ---------------- static device state (no allocations allowed) --------------
__device__ double g_ssim_sum[5];
__device__ double g_cs_sum[5];
__device__ int    g_fmax[5];
__device__ int    g_fmin[5];

// intermediates stored as fp16
__device__ __half g_s1[67829760];  // [5][2][S][S][WP]   level0
__device__ __half g_s2[64289280];  // [5][2][S][Ho][WP]  level0
// pooled pyramids (levels 1..4), fp32
__device__ float g_p1[2021760];
__device__ float g_p2[2021760];

static const long h_off[5] = {0, 0, 1769472, 1990656, 2018304};

// ---- half4 <-> float4 helpers ----------------------------------------------
__device__ __forceinline__ uint2 f4_to_h4(float4 v) {
    __half2 lo = __floats2half2_rn(v.x, v.y);
    __half2 hi = __floats2half2_rn(v.z, v.w);
    uint2 r;
    r.x = *(unsigned*)&lo;
    r.y = *(unsigned*)&hi;
    return r;
}

// ---------------------------------------------------------------------------
__global__ void k_init() {
    int t = threadIdx.x;
    if (t < 5) {
        g_ssim_sum[t] = 0.0;
        g_cs_sum[t]   = 0.0;
        g_fmax[t]     = 0;
        g_fmin[t]     = 0;
    }
}

// ------------- pass 1: W-conv (fp32) + fused 2x2x2 avg-pool + flags ---------
template <int S>
__global__ void k_pass1(const float* __restrict__ i1_0,
                        const float* __restrict__ i2_0, int lvl,
                        long poff_in, long poff_out) {
    constexpr int  Wo  = S - 10;
    constexpr int  WP  = (Wo + 3) & ~3;
    constexpr int  WP4 = WP / 4;
    constexpr int  SP  = S + 8;
    constexpr int  T   = S / 2;
    constexpr int  BT  = (4 * WP4 < 64) ? 64 : 4 * WP4;
    constexpr long FSZ = 2L * S * S * WP;

    __shared__ float s1[4 * SP];
    __shared__ float s2[4 * SP];
    __shared__ int   sfl;

    const float* i1 = (lvl == 0) ? i1_0 : (g_p1 + poff_in);
    const float* i2 = (lvl == 0) ? i2_0 : (g_p2 + poff_in);

    const int tid = threadIdx.x;
    int bid = blockIdx.x;
    int hp  = bid % (S / 2);
    int t0  = bid / (S / 2);
    int dp  = t0 % (S / 2);
    int b   = t0 / (S / 2);
    if (tid == 0) sfl = 0;

    bool mx = false, mn = false;
    for (int idx = tid; idx < 4 * SP; idx += BT) {
        int r  = idx / SP, ii = idx - r * SP;
        int d  = 2 * dp + (r >> 1);
        int h  = 2 * hp + (r & 1);
        float v1 = 0.f, v2 = 0.f;
        if (ii < S) {
            long gb = (((long)b * S + d) * S + h) * S + ii;
            v1 = i1[gb];
            v2 = i2[gb];
        }
        s1[idx] = v1;
        s2[idx] = v2;
        mx |= (v1 > 128.0f);
        mn |= (v1 < -0.5f);
    }
    __syncthreads();
    if (mx | mn) atomicOr(&sfl, (mx ? 1 : 0) | (mn ? 2 : 0));

    for (int task = tid; task < 4 * WP4; task += BT) {
        int r = task / WP4, q = task - r * WP4;
        int d = 2 * dp + (r >> 1);
        int h = 2 * hp + (r & 1);
        float xs[16], ys[16];
        {
            const float4* p1 = (const float4*)&s1[r * SP + 4 * q];
            const float4* p2 = (const float4*)&s2[r * SP + 4 * q];
#pragma unroll
            for (int m = 0; m < 4; m++) {
                float4 a = p1[m], bb = p2[m];
                xs[4 * m] = a.x;  xs[4 * m + 1] = a.y;  xs[4 * m + 2] = a.z;  xs[4 * m + 3] = a.w;
                ys[4 * m] = bb.x; ys[4 * m + 1] = bb.y; ys[4 * m + 2] = bb.z; ys[4 * m + 3] = bb.w;
            }
        }
        float xx[14], yy[14], xy[14];
#pragma unroll
        for (int m = 0; m < 14; m++) {
            xx[m] = xs[m] * xs[m];
            yy[m] = ys[m] * ys[m];
            xy[m] = xs[m] * ys[m];
        }
        float a1[4] = {0, 0, 0, 0}, a2[4] = {0, 0, 0, 0}, b1[4] = {0, 0, 0, 0},
              b2[4] = {0, 0, 0, 0}, b3[4] = {0, 0, 0, 0};
#pragma unroll
        for (int k = 0; k < WSZ; k++) {
            const float w = CW1[k];
#pragma unroll
            for (int j = 0; j < 4; j++) {
                a1[j] = fmaf(w, xs[k + j], a1[j]);
                a2[j] = fmaf(w, ys[k + j], a2[j]);
                b1[j] = fmaf(w, xx[k + j], b1[j]);
                b2[j] = fmaf(w, yy[k + j], b2[j]);
                b3[j] = fmaf(w, xy[k + j], b3[j]);
            }
        }
        long grow = ((long)b * S + d) * S + h;
        long o    = grow * WP + 4 * q;
        *(uint2*)&g_s1[o]           = f4_to_h4(make_float4(a1[0], a1[1], a1[2], a1[3]));
        *(uint2*)&g_s1[FSZ + o]     = f4_to_h4(make_float4(a2[0], a2[1], a2[2], a2[3]));
        *(uint2*)&g_s1[2 * FSZ + o] = f4_to_h4(make_float4(b1[0], b1[1], b1[2], b1[3]));
        *(uint2*)&g_s1[3 * FSZ + o] = f4_to_h4(make_float4(b2[0], b2[1], b2[2], b2[3]));
        *(uint2*)&g_s1[4 * FSZ + o] = f4_to_h4(make_float4(b3[0], b3[1], b3[2], b3[3]));
    }

    if (lvl < 4) {
        float* o1 = g_p1 + poff_out;
        float* o2 = g_p2 + poff_out;
        long orow = (((long)b * T + dp) * T + hp) * T;
        for (int x = tid; x < T; x += BT) {
            float r1 = 0.f, r2 = 0.f;
#pragma unroll
            for (int r = 0; r < 4; r++) {
                r1 += s1[r * SP + 2 * x] + s1[r * SP + 2 * x + 1];
                r2 += s2[r * SP + 2 * x] + s2[r * SP + 2 * x + 1];
            }
            o1[orow + x] = r1 * 0.125f;
            o2[orow + x] = r2 * 0.125f;
        }
    }

    __syncthreads();
    if (tid == 0 && sfl) {
        if ((sfl & 1) && !g_fmax[lvl]) atomicOr(&g_fmax[lvl], 1);
        if ((sfl & 2) && !g_fmin[lvl]) atomicOr(&g_fmin[lvl], 1);
    }
}

// ------------- pass 2: H-conv, HFMA2, TH outputs per thread -----------------
template <int S>
__global__ void k_pass2() {
    constexpr int Wo = S - 10, Ho = S - 10;
    constexpr int WP  = (Wo + 3) & ~3;
    constexpr int NQ  = WP / 4;
    constexpr int TH  = 12;
    constexpr int NHT = (Ho + TH - 1) / TH;
    constexpr int TOT = 10 * S * NHT * NQ;

    int idx = blockIdx.x * blockDim.x + threadIdx.x;
    if (idx >= TOT) return;
    int quad = idx % NQ;
    int t    = idx / NQ;
    int ht   = t % NHT;
    int q    = t / NHT;
    int ho0  = ht * TH;

    const __half* in = g_s1 + (long)q * S * WP + quad * 4;
    __half2 accA[TH], accB[TH];
    const __half2 z = __float2half2_rn(0.f);
#pragma unroll
    for (int j = 0; j < TH; j++) { accA[j] = z; accB[j] = z; }

#pragma unroll
    for (int k = 0; k < TH + 10; k++) {
        int h = ho0 + k;
        if (h < S) {
            uint2 u = *(const uint2*)(in + (long)h * WP);
            __half2 vA = *(__half2*)&u.x;
            __half2 vB = *(__half2*)&u.y;
#pragma unroll
            for (int j = 0; j < TH; j++) {
                int tt = k - j;
                if (tt >= 0 && tt < WSZ) {
                    __half2 w = u2h2(CWH[tt]);
                    accA[j] = __hfma2(w, vA, accA[j]);
                    accB[j] = __hfma2(w, vB, accB[j]);
                }
            }
        }
    }
    __half* out = g_s2 + (long)q * Ho * WP + quad * 4;
#pragma unroll
    for (int j = 0; j < TH; j++) {
        int ho = ho0 + j;
        if (ho < Ho) {
            uint2 u;
            u.x = *(unsigned*)&accA[j];
            u.y = *(unsigned*)&accB[j];
            *(uint2*)(out + (long)ho * WP) = u;
        }
    }
}

// ------------- pass 3: D-conv (HFMA2) + SSIM/CS (fp32) + reduction ----------
__device__ __forceinline__ float warp_sum(float v) {
#pragma unroll
    for (int o = 16; o; o >>= 1) v += __shfl_down_sync(0xffffffffu, v, o);
    return v;
}

template <int S>
__global__ void k_pass3(int lvl) {
    constexpr int  Wo  = S - 10, Ho = Wo, Do = Wo;
    constexpr int  WP  = (Wo + 3) & ~3;
    constexpr int  NQ2 = WP / 2;
    constexpr int  TD  = 6;
    constexpr int  NDT = (Do + TD - 1) / TD;
    constexpr long HWP = (long)Ho * WP;
    constexpr long FST = 2L * S * HWP;
    constexpr int  TOT = 2 * NDT * Ho * NQ2;

    int idx = blockIdx.x * blockDim.x + threadIdx.x;
    float sum_s = 0.f, sum_c = 0.f;
    if (idx < TOT) {
        int p  = idx % NQ2;
        int t  = idx / NQ2;
        int ho = t % Ho;
        int t2 = t / Ho;
        int dt = t2 % NDT;
        int b  = t2 / NDT;
        int d0 = dt * TD;

        const __half* base = g_s2 + (long)b * S * HWP + (long)ho * WP + 2 * p;
        __half2 A0[TD], A1[TD], A2[TD], A3[TD], A4[TD];
        const __half2 z = __float2half2_rn(0.f);
#pragma unroll
        for (int j = 0; j < TD; j++) { A0[j] = A1[j] = A2[j] = A3[j] = A4[j] = z; }
#pragma unroll
        for (int k = 0; k < TD + 10; k++) {
            int d = d0 + k;
            if (d < S) {
                const __half* pp = base + (long)d * HWP;
                __half2 v0 = *(const __half2*)(pp);
                __half2 v1 = *(const __half2*)(pp + FST);
                __half2 v2 = *(const __half2*)(pp + 2 * FST);
                __half2 v3 = *(const __half2*)(pp + 3 * FST);
                __half2 v4 = *(const __half2*)(pp + 4 * FST);
#pragma unroll
                for (int j = 0; j < TD; j++) {
                    int tt = k - j;
                    if (tt >= 0 && tt < WSZ) {
                        __half2 w = u2h2(CWH[tt]);
                        A0[j] = __hfma2(w, v0, A0[j]);
                        A1[j] = __hfma2(w, v1, A1[j]);
                        A2[j] = __hfma2(w, v2, A2[j]);
                        A3[j] = __hfma2(w, v3, A3[j]);
                        A4[j] = __hfma2(w, v4, A4[j]);
                    }
                }
            }
        }
        float maxv = g_fmax[lvl] ? 255.0f : 1.0f;
        float minv = g_fmin[lvl] ? -1.0f : 0.0f;
        float L  = maxv - minv;
        float C1 = (0.01f * L) * (0.01f * L);
        float C2 = (0.03f * L) * (0.03f * L);
        bool lane0 = (2 * p) < Wo;
        bool lane1 = (2 * p + 1) < Wo;
#pragma unroll
        for (int j = 0; j < TD; j++) {
            if (d0 + j < Do) {
                float2 m1 = __half22float2(A0[j]);
                float2 m2 = __half22float2(A1[j]);
                float2 q1 = __half22float2(A2[j]);
                float2 q2 = __half22float2(A3[j]);
                float2 q3 = __half22float2(A4[j]);
                if (lane0) {
                    float mu1 = m1.x, mu2 = m2.x;
                    float v1 = 2.0f * (q3.x - mu1 * mu2) + C2;
                    float v2 = (q1.x - mu1 * mu1) + (q2.x - mu2 * mu2) + C2;
                    sum_c += v1 / v2;
                    sum_s += (2.0f * mu1 * mu2 + C1) * v1 /
                             ((mu1 * mu1 + mu2 * mu2 + C1) * v2);
                }
                if (lane1) {
                    float mu1 = m1.y, mu2 = m2.y;
                    float v1 = 2.0f * (q3.y - mu1 * mu2) + C2;
                    float v2 = (q1.y - mu1 * mu1) + (q2.y - mu2 * mu2) + C2;
                    sum_c += v1 / v2;
                    sum_s += (2.0f * mu1 * mu2 + C1) * v1 /
                             ((mu1 * mu1 + mu2 * mu2 + C1) * v2);
                }
            }
        }
    }
    sum_c = warp_sum(sum_c);
    sum_s = warp_sum(sum_s);
    __shared__ float shc[4], shs[4];
    int lane = threadIdx.x & 31, wid = threadIdx.x >> 5;
    if (lane == 0) { shc[wid] = sum_c; shs[wid] = sum_s; }
    __syncthreads();
    if (threadIdx.x == 0) {
        float tc = shc[0] + shc[1] + shc[2] + shc[3];
        float ts = shs[0] + shs[1] + shs[2] + shs[3];
        atomicAdd(&g_cs_sum[lvl],   (double)tc);
        atomicAdd(&g_ssim_sum[lvl], (double)ts);
    }
}

// ------------- final combine -------------------------------------------------
__global__ void k_final(float* out) {
    const double W[5]   = {0.0448, 0.2856, 0.3001, 0.2363, 0.1333};
    const double cnt[5] = {12057136.0, 1272112.0, 109744.0, 5488.0, 16.0};
    double p = 1.0;
    for (int l = 0; l < 4; l++) p *= pow(g_cs_sum[l] / cnt[l], W[l]);
    p *= pow(g_ssim_sum[4] / cnt[4], W[4]);
    out[0] = (float)p;
}

// ---------------------------------------------------------------------------
template <int S>
static void run_level(const float* i1, const float* i2, int lvl,
                      long poff_in, long poff_out) {
    constexpr int Wo  = S - 10;
    constexpr int WP  = (Wo + 3) & ~3;
    constexpr int WP4 = WP / 4;
    constexpr int BT  = (4 * WP4 < 64) ? 64 : 4 * WP4;
    int nblk = 2 * (S / 2) * (S / 2);
    k_pass1<S><<<nblk, BT>>>(i1, i2, lvl, poff_in, poff_out);

    constexpr int TH = 12, NHT = (Wo + TH - 1) / TH, NQ = WP / 4;
    int tot2 = 10 * S * NHT * NQ;
    k_pass2<S><<<(tot2 + 127) / 128, 128>>>();

    constexpr int TD = 6, NDT = (Wo + TD - 1) / TD, NQ2 = WP / 2;
    int tot3 = 2 * NDT * Wo * NQ2;
    k_pass3<S><<<(tot3 + 127) / 128, 128>>>(lvl);
}

extern "C" void kernel_launch(void* const* d_in, const int* in_sizes, int n_in,
                              void* d_out, int out_size) {
    const float* img1 = (const float*)d_in[0];
    const float* img2 = (const float*)d_in[1];

    k_init<<<1, 32>>>();
    run_level<192>(img1, img2, 0, 0,        h_off[1]);
    run_level<96>(img1, img2, 1, h_off[1], h_off[2]);
    run_level<48 >(img1, img2, 2, h_off[2], h_off[3]);
    run_level<24 >(img1, img2, 3, h_off[3], h_off[4]);
    run_level<12 >(img1, img2, 4, h_off[4], 0);
    k_final<<<1, 1>>>((float*)d_out);
}

// round 12
// speedup vs baseline: 1.2716x; 1.0977x over previous
#include <cuda_runtime.h>
#include <cuda_fp16.h>
#include <math.h>

#define WSZ 11

// Gaussian weights (sigma=1.5, ws=11), fp32 exact
__device__ constexpr float CWA[WSZ] = {
    0.00102838f, 0.00759875f, 0.03600080f, 0.10936069f, 0.21300554f,
    0.26601173f, 0.21300554f, 0.10936069f, 0.03600080f, 0.00759875f,
    0.00102838f};
constexpr float CWAH[WSZ] = {
    0.00102838f, 0.00759875f, 0.03600080f, 0.10936069f, 0.21300554f,
    0.26601173f, 0.21300554f, 0.10936069f, 0.03600080f, 0.00759875f,
    0.00102838f};

// ---- compile-time float<->half converters ----------------------------------
constexpr unsigned short F2H(float f) {
    unsigned u = __builtin_bit_cast(unsigned int, f);
    unsigned sign = (u >> 16) & 0x8000u;
    int exp = (int)((u >> 23) & 0xffu) - 127 + 15;
    unsigned man = u & 0x7fffffu;
    unsigned base = ((unsigned)exp << 10) | (man >> 13);
    unsigned rem = man & 0x1fffu;
    if (rem > 0x1000u || (rem == 0x1000u && (base & 1u))) base++;
    return (unsigned short)(sign | base);
}
constexpr float H2F(unsigned short h) {
    int e = (h >> 10) & 31;
    unsigned m = h & 1023u;
    float f = 1.0f + (float)m / 1024.0f;
    int k = e - 15;
    while (k > 0) { f *= 2.0f; k--; }
    while (k < 0) { f *= 0.5f; k++; }
    return f;
}
constexpr unsigned HSPLAT(float f) {
    unsigned short h = F2H(f);
    return ((unsigned)h << 16) | h;
}
// exact sum of half-rounded weights
constexpr float SHSUM() {
    float s = 0.f;
    for (int i = 0; i < WSZ; i++) s += H2F(F2H(CWAH[i]));
    return s;
}
constexpr float SH3F() { float s = SHSUM(); return s * s * s; }
constexpr float SH6F() { float s = SH3F(); return s * s; }
// C1/C2 scale factors matching the SH^3 composite field scale
__device__ constexpr float SC2 = SH3F();
__device__ constexpr float SC1 = SH6F();
// half2-splat weights for all passes
__device__ constexpr unsigned CWH[WSZ] = {
    HSPLAT(CWAH[0]), HSPLAT(CWAH[1]), HSPLAT(CWAH[2]), HSPLAT(CWAH[3]),
    HSPLAT(CWAH[4]), HSPLAT(CWAH[5]), HSPLAT(CWAH[6]), HSPLAT(CWAH[7]),
    HSPLAT(CWAH[8]), HSPLAT(CWAH[9]), HSPLAT(CWAH[10])};

__device__ __forceinline__ __half2 u2h2(unsigned u) {
    return *(__half2*)&u;
}
// misaligned pair: (high(a), low(b))
__device__ __forceinline__ __half2 mkpair(__half2 a, __half2 b) {
    return __halves2half2(__high2half(a), __low2half(b));
}

// ---------------- static device state (no allocations allowed) --------------
__device__ double g_ssim_sum[5];
__device__ double g_cs_sum[5];
__device__ int    g_fmax[5];
__device__ int    g_fmin[5];

// intermediates stored as fp16
__device__ __half g_s1[67829760];  // [5][2][S][S][WP]   level0
__device__ __half g_s2[64289280];  // [5][2][S][Ho][WP]  level0
// pooled pyramids (levels 1..4), fp32
__device__ float g_p1[2021760];
__device__ float g_p2[2021760];

static const long h_off[5] = {0, 0, 1769472, 1990656, 2018304};

// ---------------------------------------------------------------------------
__global__ void k_init() {
    int t = threadIdx.x;
    if (t < 5) {
        g_ssim_sum[t] = 0.0;
        g_cs_sum[t]   = 0.0;
        g_fmax[t]     = 0;
        g_fmin[t]     = 0;
    }
}

// ------------- pass 1: W-conv (half2) + fused 2x2x2 avg-pool + flags --------
template <int S>
__global__ void k_pass1(const float* __restrict__ i1_0,
                        const float* __restrict__ i2_0, int lvl,
                        long poff_in, long poff_out) {
    constexpr int  Wo  = S - 10;
    constexpr int  WP  = (Wo + 3) & ~3;
    constexpr int  WP4 = WP / 4;
    constexpr int  SP  = S + 8;                 // mult of 4
    constexpr int  T   = S / 2;
    constexpr int  BT  = (4 * WP4 < 64) ? 64 : 4 * WP4;
    constexpr long FSZ = 2L * S * S * WP;

    __shared__ __half s1h[4 * SP];
    __shared__ __half s2h[4 * SP];
    __shared__ int    sfl;

    const float* i1 = (lvl == 0) ? i1_0 : (g_p1 + poff_in);
    const float* i2 = (lvl == 0) ? i2_0 : (g_p2 + poff_in);

    const int tid = threadIdx.x;
    int bid = blockIdx.x;
    int hp  = bid % (S / 2);
    int t0  = bid / (S / 2);
    int dp  = t0 % (S / 2);
    int b   = t0 / (S / 2);
    if (tid == 0) sfl = 0;

    bool mx = false, mn = false;
    for (int idx = tid; idx < 4 * SP; idx += BT) {
        int r  = idx / SP, ii = idx - r * SP;
        int d  = 2 * dp + (r >> 1);
        int h  = 2 * hp + (r & 1);
        float v1 = 0.f, v2 = 0.f;
        if (ii < S) {
            long gb = (((long)b * S + d) * S + h) * S + ii;
            v1 = i1[gb];
            v2 = i2[gb];
        }
        s1h[idx] = __float2half(v1);
        s2h[idx] = __float2half(v2);
        mx |= (v1 > 128.0f);
        mn |= (v1 < -0.5f);
    }
    __syncthreads();
    if (mx | mn) atomicOr(&sfl, (mx ? 1 : 0) | (mn ? 2 : 0));

    for (int task = tid; task < 4 * WP4; task += BT) {
        int r = task / WP4, q = task - r * WP4;
        int d = 2 * dp + (r >> 1);
        int h = 2 * hp + (r & 1);

        // 16 input halfs = 8 aligned pairs
        __half2 ax[8], ay[8];
        {
            const uint2* p1 = (const uint2*)&s1h[r * SP + 4 * q];
            const uint2* p2 = (const uint2*)&s2h[r * SP + 4 * q];
#pragma unroll
            for (int m = 0; m < 4; m++) {
                uint2 u1 = p1[m], u2 = p2[m];
                ax[2 * m]     = *(__half2*)&u1.x;
                ax[2 * m + 1] = *(__half2*)&u1.y;
                ay[2 * m]     = *(__half2*)&u2.x;
                ay[2 * m + 1] = *(__half2*)&u2.y;
            }
        }
        // misaligned pairs (shared by all fields)
        __half2 mxp[6], myp[6];
#pragma unroll
        for (int i = 0; i < 6; i++) {
            mxp[i] = mkpair(ax[i], ax[i + 1]);
            myp[i] = mkpair(ay[i], ay[i + 1]);
        }
        // products
        __half2 axx[7], ayy[7], axy[7], mxx[6], myy[6], mxy[6];
#pragma unroll
        for (int i = 0; i < 7; i++) {
            axx[i] = __hmul2(ax[i], ax[i]);
            ayy[i] = __hmul2(ay[i], ay[i]);
            axy[i] = __hmul2(ax[i], ay[i]);
        }
#pragma unroll
        for (int i = 0; i < 6; i++) {
            mxx[i] = __hmul2(mxp[i], mxp[i]);
            myy[i] = __hmul2(myp[i], myp[i]);
            mxy[i] = __hmul2(mxp[i], myp[i]);
        }

        uint2 o1v, o2v, o3v, o4v, o5v;
        const __half2 z = __float2half2_rn(0.f);
#pragma unroll
        for (int j = 0; j < 2; j++) {
            __half2 A1 = z, A2 = z, B1 = z, B2 = z, B3 = z;
#pragma unroll
            for (int k = 0; k < WSZ; k++) {
                __half2 w = u2h2(CWH[k]);
                if ((k & 1) == 0) {
                    int i = j + (k >> 1);
                    A1 = __hfma2(w, ax[i],  A1);
                    A2 = __hfma2(w, ay[i],  A2);
                    B1 = __hfma2(w, axx[i], B1);
                    B2 = __hfma2(w, ayy[i], B2);
                    B3 = __hfma2(w, axy[i], B3);
                } else {
                    int i = j + ((k - 1) >> 1);
                    A1 = __hfma2(w, mxp[i], A1);
                    A2 = __hfma2(w, myp[i], A2);
                    B1 = __hfma2(w, mxx[i], B1);
                    B2 = __hfma2(w, myy[i], B2);
                    B3 = __hfma2(w, mxy[i], B3);
                }
            }
            unsigned* dst1 = (j == 0) ? &o1v.x : &o1v.y;
            unsigned* dst2 = (j == 0) ? &o2v.x : &o2v.y;
            unsigned* dst3 = (j == 0) ? &o3v.x : &o3v.y;
            unsigned* dst4 = (j == 0) ? &o4v.x : &o4v.y;
            unsigned* dst5 = (j == 0) ? &o5v.x : &o5v.y;
            *dst1 = *(unsigned*)&A1;
            *dst2 = *(unsigned*)&A2;
            *dst3 = *(unsigned*)&B1;
            *dst4 = *(unsigned*)&B2;
            *dst5 = *(unsigned*)&B3;
        }
        long grow = ((long)b * S + d) * S + h;
        long o    = grow * WP + 4 * q;
        *(uint2*)&g_s1[o]           = o1v;
        *(uint2*)&g_s1[FSZ + o]     = o2v;
        *(uint2*)&g_s1[2 * FSZ + o] = o3v;
        *(uint2*)&g_s1[3 * FSZ + o] = o4v;
        *(uint2*)&g_s1[4 * FSZ + o] = o5v;
    }

    if (lvl < 4) {
        float* o1 = g_p1 + poff_out;
        float* o2 = g_p2 + poff_out;
        long orow = (((long)b * T + dp) * T + hp) * T;
        for (int x = tid; x < T; x += BT) {
            float r1 = 0.f, r2 = 0.f;
#pragma unroll
            for (int r = 0; r < 4; r++) {
                float2 a = __half22float2(*(const __half2*)&s1h[r * SP + 2 * x]);
                float2 c = __half22float2(*(const __half2*)&s2h[r * SP + 2 * x]);
                r1 += a.x + a.y;
                r2 += c.x + c.y;
            }
            o1[orow + x] = r1 * 0.125f;
            o2[orow + x] = r2 * 0.125f;
        }
    }

    __syncthreads();
    if (tid == 0 && sfl) {
        if ((sfl & 1) && !g_fmax[lvl]) atomicOr(&g_fmax[lvl], 1);
        if ((sfl & 2) && !g_fmin[lvl]) atomicOr(&g_fmin[lvl], 1);
    }
}

// ------------- pass 2: H-conv, HFMA2, TH outputs per thread -----------------
template <int S>
__global__ void k_pass2() {
    constexpr int Wo = S - 10, Ho = S - 10;
    constexpr int WP  = (Wo + 3) & ~3;
    constexpr int NQ  = WP / 4;
    constexpr int TH  = 12;
    constexpr int NHT = (Ho + TH - 1) / TH;
    constexpr int TOT = 10 * S * NHT * NQ;

    int idx = blockIdx.x * blockDim.x + threadIdx.x;
    if (idx >= TOT) return;
    int quad = idx % NQ;
    int t    = idx / NQ;
    int ht   = t % NHT;
    int q    = t / NHT;
    int ho0  = ht * TH;

    const __half* in = g_s1 + (long)q * S * WP + quad * 4;
    __half2 accA[TH], accB[TH];
    const __half2 z = __float2half2_rn(0.f);
#pragma unroll
    for (int j = 0; j < TH; j++) { accA[j] = z; accB[j] = z; }

#pragma unroll
    for (int k = 0; k < TH + 10; k++) {
        int h = ho0 + k;
        if (h < S) {
            uint2 u = *(const uint2*)(in + (long)h * WP);
            __half2 vA = *(__half2*)&u.x;
            __half2 vB = *(__half2*)&u.y;
#pragma unroll
            for (int j = 0; j < TH; j++) {
                int tt = k - j;
                if (tt >= 0 && tt < WSZ) {
                    __half2 w = u2h2(CWH[tt]);
                    accA[j] = __hfma2(w, vA, accA[j]);
                    accB[j] = __hfma2(w, vB, accB[j]);
                }
            }
        }
    }
    __half* out = g_s2 + (long)q * Ho * WP + quad * 4;
#pragma unroll
    for (int j = 0; j < TH; j++) {
        int ho = ho0 + j;
        if (ho < Ho) {
            uint2 u;
            u.x = *(unsigned*)&accA[j];
            u.y = *(unsigned*)&accB[j];
            *(uint2*)(out + (long)ho * WP) = u;
        }
    }
}

// ------------- pass 3: D-conv (HFMA2) + SSIM/CS (fp32) + reduction ----------
__device__ __forceinline__ float warp_sum(float v) {
#pragma unroll
    for (int o = 16; o; o >>= 1) v += __shfl_down_sync(0xffffffffu, v, o);
    return v;
}

template <int S>
__global__ void k_pass3(int lvl) {
    constexpr int  Wo  = S - 10, Ho = Wo, Do = Wo;
    constexpr int  WP  = (Wo + 3) & ~3;
    constexpr int  NQ2 = WP / 2;
    constexpr int  TD  = 6;
    constexpr int  NDT = (Do + TD - 1) / TD;
    constexpr long HWP = (long)Ho * WP;
    constexpr long FST = 2L * S * HWP;
    constexpr int  TOT = 2 * NDT * Ho * NQ2;

    int idx = blockIdx.x * blockDim.x + threadIdx.x;
    float sum_s = 0.f, sum_c = 0.f;
    if (idx < TOT) {
        int p  = idx % NQ2;
        int t  = idx / NQ2;
        int ho = t % Ho;
        int t2 = t / Ho;
        int dt = t2 % NDT;
        int b  = t2 / NDT;
        int d0 = dt * TD;

        const __half* base = g_s2 + (long)b * S * HWP + (long)ho * WP + 2 * p;
        __half2 A0[TD], A1[TD], A2[TD], A3[TD], A4[TD];
        const __half2 z = __float2half2_rn(0.f);
#pragma unroll
        for (int j = 0; j < TD; j++) { A0[j] = A1[j] = A2[j] = A3[j] = A4[j] = z; }
#pragma unroll
        for (int k = 0; k < TD + 10; k++) {
            int d = d0 + k;
            if (d < S) {
                const __half* pp = base + (long)d * HWP;
                __half2 v0 = *(const __half2*)(pp);
                __half2 v1 = *(const __half2*)(pp + FST);
                __half2 v2 = *(const __half2*)(pp + 2 * FST);
                __half2 v3 = *(const __half2*)(pp + 3 * FST);
                __half2 v4 = *(const __half2*)(pp + 4 * FST);
#pragma unroll
                for (int j = 0; j < TD; j++) {
                    int tt = k - j;
                    if (tt >= 0 && tt < WSZ) {
                        __half2 w = u2h2(CWH[tt]);
                        A0[j] = __hfma2(w, v0, A0[j]);
                        A1[j] = __hfma2(w, v1, A1[j]);
                        A2[j] = __hfma2(w, v2, A2[j]);
                        A3[j] = __hfma2(w, v3, A3[j]);
                        A4[j] = __hfma2(w, v4, A4[j]);
                    }
                }
            }
        }
        float maxv = g_fmax[lvl] ? 255.0f : 1.0f;
        float minv = g_fmin[lvl] ? -1.0f : 0.0f;
        float L  = maxv - minv;
        // C1/C2 scaled to match the SH^3 composite half-weight field scale
        float C1 = (0.01f * L) * (0.01f * L) * SC1;
        float C2 = (0.03f * L) * (0.03f * L) * SC2;
        bool lane0 = (2 * p) < Wo;
        bool lane1 = (2 * p + 1) < Wo;
#pragma unroll
        for (int j = 0; j < TD; j++) {
            if (d0 + j < Do) {
                float2 m1 = __half22float2(A0[j]);
                float2 m2 = __half22float2(A1[j]);
                float2 q1 = __half22float2(A2[j]);
                float2 q2 = __half22float2(A3[j]);
                float2 q3 = __half22float2(A4[j]);
                if (lane0) {
                    float mu1 = m1.x, mu2 = m2.x;
                    float v1 = 2.0f * (q3.x - mu1 * mu2) + C2;
                    float v2 = (q1.x - mu1 * mu1) + (q2.x - mu2 * mu2) + C2;
                    sum_c += v1 / v2;
                    sum_s += (2.0f * mu1 * mu2 + C1) * v1 /
                             ((mu1 * mu1 + mu2 * mu2 + C1) * v2);
                }
                if (lane1) {
                    float mu1 = m1.y, mu2 = m2.y;
                    float v1 = 2.0f * (q3.y - mu1 * mu2) + C2;
                    float v2 = (q1.y - mu1 * mu1) + (q2.y - mu2 * mu2) + C2;
                    sum_c += v1 / v2;
                    sum_s += (2.0f * mu1 * mu2 + C1) * v1 /
                             ((mu1 * mu1 + mu2 * mu2 + C1) * v2);
                }
            }
        }
    }
    sum_c = warp_sum(sum_c);
    sum_s = warp_sum(sum_s);
    __shared__ float shc[4], shs[4];
    int lane = threadIdx.x & 31, wid = threadIdx.x >> 5;
    if (lane == 0) { shc[wid] = sum_c; shs[wid] = sum_s; }
    __syncthreads();
    if (threadIdx.x == 0) {
        float tc = shc[0] + shc[1] + shc[2] + shc[3];
        float ts = shs[0] + shs[1] + shs[2] + shs[3];
        atomicAdd(&g_cs_sum[lvl],   (double)tc);
        atomicAdd(&g_ssim_sum[lvl], (double)ts);
    }
}

// ------------- final combine -------------------------------------------------
__global__ void k_final(float* out) {
    const double W[5]   = {0.0448, 0.2856, 0.3001, 0.2363, 0.1333};
    const double cnt[5] = {12057136.0, 1272112.0, 109744.0, 5488.0, 16.0};
    double p = 1.0;
    for (int l = 0; l < 4; l++) p *= pow(g_cs_sum[l] / cnt[l], W[l]);
    p *= pow(g_ssim_sum[4] / cnt[4], W[4]);
    out[0] = (float)p;
}

// ---------------------------------------------------------------------------
template <int S>
static void run_level(const float* i1, const float* i2, int lvl,
                      long poff_in, long poff_out) {
    constexpr int Wo  = S - 10;
    constexpr int WP  = (Wo + 3) & ~3;
    constexpr int WP4 = WP / 4;
    constexpr int BT  = (4 * WP4 < 64) ? 64 : 4 * WP4;
    int nblk = 2 * (S / 2) * (S / 2);
    k_pass1<S><<<nblk, BT>>>(i1, i2, lvl, poff_in, poff_out);

    constexpr int TH = 12, NHT = (Wo + TH - 1) / TH, NQ = WP / 4;
    int tot2 = 10 * S * NHT * NQ;
    k_pass2<S><<<(tot2 + 127) / 128, 128>>>();

    constexpr int TD = 6, NDT = (Wo + TD - 1) / TD, NQ2 = WP / 2;
    int tot3 = 2 * NDT * Wo * NQ2;
    k_pass3<S><<<(tot3 + 127) / 128, 128>>>(lvl);
}

extern "C" void kernel_launch(void* const* d_in, const int* in_sizes, int n_in,
                              void* d_out, int out_size) {
    const float* img1 = (const float*)d_in[0];
    const float* img2 = (const float*)d_in[1];

    k_init<<<1, 32>>>();
    run_level<192>(img1, img2, 0, 0,        h_off[1]);
    run_level<96>(img1, img2, 1, h_off[1], h_off[2]);
    run_level<48 >(img1, img2, 2, h_off[2], h_off[3]);
    run_level<24 >(img1, img2, 3, h_off[3], h_off[4]);
    run_level<12 >(img1, img2, 4, h_off[4], 0);
    k_final<<<1, 1>>>((float*)d_out);
}

// round 13
// speedup vs baseline: 1.3115x; 1.0314x over previous
#include <cuda_runtime.h>
#include <cuda_fp16.h>
#include <math.h>

#define WSZ 11

constexpr float CWAH[WSZ] = {
    0.00102838f, 0.00759875f, 0.03600080f, 0.10936069f, 0.21300554f,
    0.26601173f, 0.21300554f, 0.10936069f, 0.03600080f, 0.00759875f,
    0.00102838f};

// ---- compile-time float<->half converters ----------------------------------
__host__ __device__ constexpr unsigned short F2H(float f) {
    unsigned u = __builtin_bit_cast(unsigned int, f);
    unsigned sign = (u >> 16) & 0x8000u;
    int exp = (int)((u >> 23) & 0xffu) - 127 + 15;
    unsigned man = u & 0x7fffffu;
    unsigned base = ((unsigned)exp << 10) | (man >> 13);
    unsigned rem = man & 0x1fffu;
    if (rem > 0x1000u || (rem == 0x1000u && (base & 1u))) base++;
    return (unsigned short)(sign | base);
}
__host__ __device__ constexpr float H2F(unsigned short h) {
    int e = (h >> 10) & 31;
    unsigned m = h & 1023u;
    float f = 1.0f + (float)m / 1024.0f;
    int k = e - 15;
    while (k > 0) { f *= 2.0f; k--; }
    while (k < 0) { f *= 0.5f; k++; }
    return f;
}
__host__ __device__ constexpr unsigned HSPLAT(float f) {
    unsigned short h = F2H(f);
    return ((unsigned)h << 16) | h;
}
__host__ __device__ constexpr float SHSUM() {
    float s = 0.f;
    for (int i = 0; i < WSZ; i++) s += H2F(F2H(CWAH[i]));
    return s;
}
__host__ __device__ constexpr float SH3F() { float s = SHSUM(); return s * s * s; }
__host__ __device__ constexpr float SH6F() { float s = SH3F(); return s * s; }
__device__ constexpr float SC2 = SH3F();
__device__ constexpr float SC1 = SH6F();
__device__ constexpr unsigned CWH[WSZ] = {
    HSPLAT(CWAH[0]), HSPLAT(CWAH[1]), HSPLAT(CWAH[2]), HSPLAT(CWAH[3]),
    HSPLAT(CWAH[4]), HSPLAT(CWAH[5]), HSPLAT(CWAH[6]), HSPLAT(CWAH[7]),
    HSPLAT(CWAH[8]), HSPLAT(CWAH[9]), HSPLAT(CWAH[10])};

// ---- level geometry (constexpr) ---------------------------------------------
__host__ __device__ constexpr int  LSV(int l) {
    return l == 0 ? 192 : l == 1 ? 96 : l == 2 ? 48 : l == 3 ? 24 : 12;
}
__host__ __device__ constexpr int  WPC(int S) { return ((S - 10) + 3) & ~3; }
__host__ __device__ constexpr long S1SZC(int S) { return 10L * S * S * WPC(S); }
__host__ __device__ constexpr long S2SZC(int S) { return 10L * S * (S - 10) * WPC(S); }
__host__ __device__ constexpr long S1OFF(int l) {
    long o = 0; for (int i = 0; i < l; i++) o += S1SZC(LSV(i)); return o;
}
__host__ __device__ constexpr long S2OFF(int l) {
    long o = 0; for (int i = 0; i < l; i++) o += S2SZC(LSV(i)); return o;
}
__host__ __device__ constexpr int TOT2C(int S) {
    int Wo = S - 10, NQ = WPC(S) / 4, NHT = (Wo + 11) / 12;
    return 10 * S * NHT * NQ;
}
__host__ __device__ constexpr int NB2C(int S) { return (TOT2C(S) + 127) / 128; }
__host__ __device__ constexpr int NB2CUM(int l) {
    int s = 0; for (int i = 0; i < l; i++) s += NB2C(LSV(i)); return s;
}
__host__ __device__ constexpr int TOT3C(int S) {
    int Wo = S - 10, NDT = (Wo + 5) / 6, NQ2 = WPC(S) / 2;
    return 2 * NDT * Wo * NQ2;
}
__host__ __device__ constexpr int NB3C(int S) { return (TOT3C(S) + 127) / 128; }
__host__ __device__ constexpr int NB3CUM(int l) {
    int s = 0; for (int i = 0; i < l; i++) s += NB3C(LSV(i)); return s;
}

__device__ __forceinline__ __half2 u2h2(unsigned u) { return *(__half2*)&u; }
__device__ __forceinline__ __half2 mkpair(__half2 a, __half2 b) {
    return __halves2half2(__high2half(a), __low2half(b));
}

// ---------------- static device state (no allocations allowed) --------------
__device__ double g_ssim_sum[5];
__device__ double g_cs_sum[5];
__device__ int    g_fmax[5];
__device__ int    g_fmin[5];

// per-level intermediates, fp16
__device__ __half g_s1[S1OFF(5)];
__device__ __half g_s2[S2OFF(5)];
// pooled pyramids (levels 1..4), fp32
__device__ float g_p1[2021760];
__device__ float g_p2[2021760];

static const long h_off[5] = {0, 0, 1769472, 1990656, 2018304};

// ---------------------------------------------------------------------------
__global__ void k_init() {
    int t = threadIdx.x;
    if (t < 5) {
        g_ssim_sum[t] = 0.0;
        g_cs_sum[t]   = 0.0;
        g_fmax[t]     = 0;
        g_fmin[t]     = 0;
    }
}

// ------------- pass 1: W-conv (half2) + fused 2x2x2 avg-pool + flags --------
template <int S, int LVL>
__global__ void k_pass1(const float* __restrict__ i1_0,
                        const float* __restrict__ i2_0,
                        long poff_in, long poff_out) {
    constexpr int  WP  = WPC(S);
    constexpr int  WP4 = WP / 4;
    constexpr int  SP  = S + 8;
    constexpr int  T   = S / 2;
    constexpr int  BT  = (4 * WP4 < 64) ? 64 : 4 * WP4;
    constexpr long FSZ = 2L * S * S * WP;
    constexpr long S1B = S1OFF(LVL);

    __shared__ __half s1h[4 * SP];
    __shared__ __half s2h[4 * SP];
    __shared__ int    sfl;

    const float* i1 = (LVL == 0) ? i1_0 : (g_p1 + poff_in);
    const float* i2 = (LVL == 0) ? i2_0 : (g_p2 + poff_in);

    const int tid = threadIdx.x;
    int bid = blockIdx.x;
    int hp  = bid % (S / 2);
    int t0  = bid / (S / 2);
    int dp  = t0 % (S / 2);
    int b   = t0 / (S / 2);
    if (tid == 0) sfl = 0;

    bool mx = false, mn = false;
    for (int idx = tid; idx < 4 * SP; idx += BT) {
        int r  = idx / SP, ii = idx - r * SP;
        int d  = 2 * dp + (r >> 1);
        int h  = 2 * hp + (r & 1);
        float v1 = 0.f, v2 = 0.f;
        if (ii < S) {
            long gb = (((long)b * S + d) * S + h) * S + ii;
            v1 = i1[gb];
            v2 = i2[gb];
        }
        s1h[idx] = __float2half(v1);
        s2h[idx] = __float2half(v2);
        mx |= (v1 > 128.0f);
        mn |= (v1 < -0.5f);
    }
    __syncthreads();
    if (mx | mn) atomicOr(&sfl, (mx ? 1 : 0) | (mn ? 2 : 0));

    for (int task = tid; task < 4 * WP4; task += BT) {
        int r = task / WP4, q = task - r * WP4;
        int d = 2 * dp + (r >> 1);
        int h = 2 * hp + (r & 1);

        __half2 ax[8], ay[8];
        {
            const uint2* p1 = (const uint2*)&s1h[r * SP + 4 * q];
            const uint2* p2 = (const uint2*)&s2h[r * SP + 4 * q];
#pragma unroll
            for (int m = 0; m < 4; m++) {
                uint2 u1 = p1[m], u2 = p2[m];
                ax[2 * m]     = *(__half2*)&u1.x;
                ax[2 * m + 1] = *(__half2*)&u1.y;
                ay[2 * m]     = *(__half2*)&u2.x;
                ay[2 * m + 1] = *(__half2*)&u2.y;
            }
        }
        __half2 mxp[6], myp[6];
#pragma unroll
        for (int i = 0; i < 6; i++) {
            mxp[i] = mkpair(ax[i], ax[i + 1]);
            myp[i] = mkpair(ay[i], ay[i + 1]);
        }
        __half2 axx[7], ayy[7], axy[7], mxx[6], myy[6], mxy[6];
#pragma unroll
        for (int i = 0; i < 7; i++) {
            axx[i] = __hmul2(ax[i], ax[i]);
            ayy[i] = __hmul2(ay[i], ay[i]);
            axy[i] = __hmul2(ax[i], ay[i]);
        }
#pragma unroll
        for (int i = 0; i < 6; i++) {
            mxx[i] = __hmul2(mxp[i], mxp[i]);
            myy[i] = __hmul2(myp[i], myp[i]);
            mxy[i] = __hmul2(mxp[i], myp[i]);
        }

        uint2 o1v, o2v, o3v, o4v, o5v;
        const __half2 z = __float2half2_rn(0.f);
#pragma unroll
        for (int j = 0; j < 2; j++) {
            __half2 A1 = z, A2 = z, B1 = z, B2 = z, B3 = z;
#pragma unroll
            for (int k = 0; k < WSZ; k++) {
                __half2 w = u2h2(CWH[k]);
                if ((k & 1) == 0) {
                    int i = j + (k >> 1);
                    A1 = __hfma2(w, ax[i],  A1);
                    A2 = __hfma2(w, ay[i],  A2);
                    B1 = __hfma2(w, axx[i], B1);
                    B2 = __hfma2(w, ayy[i], B2);
                    B3 = __hfma2(w, axy[i], B3);
                } else {
                    int i = j + ((k - 1) >> 1);
                    A1 = __hfma2(w, mxp[i], A1);
                    A2 = __hfma2(w, myp[i], A2);
                    B1 = __hfma2(w, mxx[i], B1);
                    B2 = __hfma2(w, myy[i], B2);
                    B3 = __hfma2(w, mxy[i], B3);
                }
            }
            unsigned* dst1 = (j == 0) ? &o1v.x : &o1v.y;
            unsigned* dst2 = (j == 0) ? &o2v.x : &o2v.y;
            unsigned* dst3 = (j == 0) ? &o3v.x : &o3v.y;
            unsigned* dst4 = (j == 0) ? &o4v.x : &o4v.y;
            unsigned* dst5 = (j == 0) ? &o5v.x : &o5v.y;
            *dst1 = *(unsigned*)&A1;
            *dst2 = *(unsigned*)&A2;
            *dst3 = *(unsigned*)&B1;
            *dst4 = *(unsigned*)&B2;
            *dst5 = *(unsigned*)&B3;
        }
        long grow = ((long)b * S + d) * S + h;
        long o    = S1B + grow * WP + 4 * q;
        *(uint2*)&g_s1[o]           = o1v;
        *(uint2*)&g_s1[FSZ + o]     = o2v;
        *(uint2*)&g_s1[2 * FSZ + o] = o3v;
        *(uint2*)&g_s1[3 * FSZ + o] = o4v;
        *(uint2*)&g_s1[4 * FSZ + o] = o5v;
    }

    if (LVL < 4) {
        float* o1 = g_p1 + poff_out;
        float* o2 = g_p2 + poff_out;
        long orow = (((long)b * T + dp) * T + hp) * T;
        for (int x = tid; x < T; x += BT) {
            float r1 = 0.f, r2 = 0.f;
#pragma unroll
            for (int r = 0; r < 4; r++) {
                float2 a = __half22float2(*(const __half2*)&s1h[r * SP + 2 * x]);
                float2 c = __half22float2(*(const __half2*)&s2h[r * SP + 2 * x]);
                r1 += a.x + a.y;
                r2 += c.x + c.y;
            }
            o1[orow + x] = r1 * 0.125f;
            o2[orow + x] = r2 * 0.125f;
        }
    }

    __syncthreads();
    if (tid == 0 && sfl) {
        if ((sfl & 1) && !g_fmax[LVL]) atomicOr(&g_fmax[LVL], 1);
        if ((sfl & 2) && !g_fmin[LVL]) atomicOr(&g_fmin[LVL], 1);
    }
}

// ------------- pass 2 body: H-conv, HFMA2, TH outputs per thread ------------
template <int S, int LVL>
__device__ __forceinline__ void pass2_body(int idx) {
    constexpr int Wo = S - 10, Ho = S - 10;
    constexpr int WP  = WPC(S);
    constexpr int NQ  = WP / 4;
    constexpr int TH  = 12;
    constexpr int NHT = (Ho + TH - 1) / TH;
    constexpr int TOT = TOT2C(S);
    constexpr long S1B = S1OFF(LVL);
    constexpr long S2B = S2OFF(LVL);

    if (idx >= TOT) return;
    int quad = idx % NQ;
    int t    = idx / NQ;
    int ht   = t % NHT;
    int q    = t / NHT;
    int ho0  = ht * TH;

    const __half* in = g_s1 + S1B + (long)q * S * WP + quad * 4;
    __half2 accA[TH], accB[TH];
    const __half2 z = __float2half2_rn(0.f);
#pragma unroll
    for (int j = 0; j < TH; j++) { accA[j] = z; accB[j] = z; }

#pragma unroll
    for (int k = 0; k < TH + 10; k++) {
        int h = ho0 + k;
        if (h < S) {
            uint2 u = *(const uint2*)(in + (long)h * WP);
            __half2 vA = *(__half2*)&u.x;
            __half2 vB = *(__half2*)&u.y;
#pragma unroll
            for (int j = 0; j < TH; j++) {
                int tt = k - j;
                if (tt >= 0 && tt < WSZ) {
                    __half2 w = u2h2(CWH[tt]);
                    accA[j] = __hfma2(w, vA, accA[j]);
                    accB[j] = __hfma2(w, vB, accB[j]);
                }
            }
        }
    }
    __half* out = g_s2 + S2B + (long)q * Ho * WP + quad * 4;
#pragma unroll
    for (int j = 0; j < TH; j++) {
        int ho = ho0 + j;
        if (ho < Ho) {
            uint2 u;
            u.x = *(unsigned*)&accA[j];
            u.y = *(unsigned*)&accB[j];
            *(uint2*)(out + (long)ho * WP) = u;
        }
    }
}

__global__ void k_pass2_all() {
    int b   = blockIdx.x;
    int tid = threadIdx.x;
    if (b < NB2CUM(1))      pass2_body<192, 0>((b - NB2CUM(0)) * 128 + tid);
    else if (b < NB2CUM(2)) pass2_body<96, 1>((b - NB2CUM(1)) * 128 + tid);
    else if (b < NB2CUM(3)) pass2_body<48, 2>((b - NB2CUM(2)) * 128 + tid);
    else if (b < NB2CUM(4)) pass2_body<24, 3>((b - NB2CUM(3)) * 128 + tid);
    else                    pass2_body<12, 4>((b - NB2CUM(4)) * 128 + tid);
}

// ------------- pass 3 body: D-conv (HFMA2) + SSIM/CS (fp32) + reduction -----
__device__ __forceinline__ float warp_sum(float v) {
#pragma unroll
    for (int o = 16; o; o >>= 1) v += __shfl_down_sync(0xffffffffu, v, o);
    return v;
}

template <int S, int LVL>
__device__ __forceinline__ void pass3_body(int idx) {
    constexpr int  Wo  = S - 10, Ho = Wo, Do = Wo;
    constexpr int  WP  = WPC(S);
    constexpr int  NQ2 = WP / 2;
    constexpr int  TD  = 6;
    constexpr int  NDT = (Do + TD - 1) / TD;
    constexpr long HWP = (long)Ho * WP;
    constexpr long FST = 2L * S * HWP;
    constexpr int  TOT = TOT3C(S);
    constexpr long S2B = S2OFF(LVL);

    float sum_s = 0.f, sum_c = 0.f;
    if (idx < TOT) {
        int p  = idx % NQ2;
        int t  = idx / NQ2;
        int ho = t % Ho;
        int t2 = t / Ho;
        int dt = t2 % NDT;
        int b  = t2 / NDT;
        int d0 = dt * TD;

        const __half* base = g_s2 + S2B + (long)b * S * HWP + (long)ho * WP + 2 * p;
        __half2 A0[TD], A1[TD], A2[TD], A3[TD], A4[TD];
        const __half2 z = __float2half2_rn(0.f);
#pragma unroll
        for (int j = 0; j < TD; j++) { A0[j] = A1[j] = A2[j] = A3[j] = A4[j] = z; }
#pragma unroll
        for (int k = 0; k < TD + 10; k++) {
            int d = d0 + k;
            if (d < S) {
                const __half* pp = base + (long)d * HWP;
                __half2 v0 = *(const __half2*)(pp);
                __half2 v1 = *(const __half2*)(pp + FST);
                __half2 v2 = *(const __half2*)(pp + 2 * FST);
                __half2 v3 = *(const __half2*)(pp + 3 * FST);
                __half2 v4 = *(const __half2*)(pp + 4 * FST);
#pragma unroll
                for (int j = 0; j < TD; j++) {
                    int tt = k - j;
                    if (tt >= 0 && tt < WSZ) {
                        __half2 w = u2h2(CWH[tt]);
                        A0[j] = __hfma2(w, v0, A0[j]);
                        A1[j] = __hfma2(w, v1, A1[j]);
                        A2[j] = __hfma2(w, v2, A2[j]);
                        A3[j] = __hfma2(w, v3, A3[j]);
                        A4[j] = __hfma2(w, v4, A4[j]);
                    }
                }
            }
        }
        float maxv = g_fmax[LVL] ? 255.0f : 1.0f;
        float minv = g_fmin[LVL] ? -1.0f : 0.0f;
        float L  = maxv - minv;
        float C1 = (0.01f * L) * (0.01f * L) * SC1;
        float C2 = (0.03f * L) * (0.03f * L) * SC2;
        bool lane0 = (2 * p) < Wo;
        bool lane1 = (2 * p + 1) < Wo;
#pragma unroll
        for (int j = 0; j < TD; j++) {
            if (d0 + j < Do) {
                float2 m1 = __half22float2(A0[j]);
                float2 m2 = __half22float2(A1[j]);
                float2 q1 = __half22float2(A2[j]);
                float2 q2 = __half22float2(A3[j]);
                float2 q3 = __half22float2(A4[j]);
                if (lane0) {
                    float mu1 = m1.x, mu2 = m2.x;
                    float v1 = 2.0f * (q3.x - mu1 * mu2) + C2;
                    float v2 = (q1.x - mu1 * mu1) + (q2.x - mu2 * mu2) + C2;
                    sum_c += v1 / v2;
                    sum_s += (2.0f * mu1 * mu2 + C1) * v1 /
                             ((mu1 * mu1 + mu2 * mu2 + C1) * v2);
                }
                if (lane1) {
                    float mu1 = m1.y, mu2 = m2.y;
                    float v1 = 2.0f * (q3.y - mu1 * mu2) + C2;
                    float v2 = (q1.y - mu1 * mu1) + (q2.y - mu2 * mu2) + C2;
                    sum_c += v1 / v2;
                    sum_s += (2.0f * mu1 * mu2 + C1) * v1 /
                             ((mu1 * mu1 + mu2 * mu2 + C1) * v2);
                }
            }
        }
    }
    sum_c = warp_sum(sum_c);
    sum_s = warp_sum(sum_s);
    __shared__ float shc[4], shs[4];
    int lane = threadIdx.x & 31, wid = threadIdx.x >> 5;
    if (lane == 0) { shc[wid] = sum_c; shs[wid] = sum_s; }
    __syncthreads();
    if (threadIdx.x == 0) {
        float tc = shc[0] + shc[1] + shc[2] + shc[3];
        float ts = shs[0] + shs[1] + shs[2] + shs[3];
        atomicAdd(&g_cs_sum[LVL],   (double)tc);
        atomicAdd(&g_ssim_sum[LVL], (double)ts);
    }
}

__global__ void k_pass3_all() {
    int b   = blockIdx.x;
    int tid = threadIdx.x;
    if (b < NB3CUM(1))      pass3_body<192, 0>((b - NB3CUM(0)) * 128 + tid);
    else if (b < NB3CUM(2)) pass3_body<96, 1>((b - NB3CUM(1)) * 128 + tid);
    else if (b < NB3CUM(3)) pass3_body<48, 2>((b - NB3CUM(2)) * 128 + tid);
    else if (b < NB3CUM(4)) pass3_body<24, 3>((b - NB3CUM(3)) * 128 + tid);
    else                    pass3_body<12, 4>((b - NB3CUM(4)) * 128 + tid);
}

// ------------- final combine -------------------------------------------------
__global__ void k_final(float* out) {
    const double W[5]   = {0.0448, 0.2856, 0.3001, 0.2363, 0.1333};
    const double cnt[5] = {12057136.0, 1272112.0, 109744.0, 5488.0, 16.0};
    double p = 1.0;
    for (int l = 0; l < 4; l++) p *= pow(g_cs_sum[l] / cnt[l], W[l]);
    p *= pow(g_ssim_sum[4] / cnt[4], W[4]);
    out[0] = (float)p;
}

// ---------------------------------------------------------------------------
template <int S, int LVL>
static void launch_pass1(const float* i1, const float* i2,
                         long poff_in, long poff_out) {
    constexpr int WP4 = WPC(S) / 4;
    constexpr int BT  = (4 * WP4 < 64) ? 64 : 4 * WP4;
    int nblk = 2 * (S / 2) * (S / 2);
    k_pass1<S, LVL><<<nblk, BT>>>(i1, i2, poff_in, poff_out);
}

extern "C" void kernel_launch(void* const* d_in, const int* in_sizes, int n_in,
                              void* d_out, int out_size) {
    const float* img1 = (const float*)d_in[0];
    const float* img2 = (const float*)d_in[1];

    k_init<<<1, 32>>>();
    launch_pass1<192, 0>(img1, img2, 0,        h_off[1]);
    launch_pass1<96, 1>(img1, img2, h_off[1], h_off[2]);
    launch_pass1<48, 2>(img1, img2, h_off[2], h_off[3]);
    launch_pass1<24, 3>(img1, img2, h_off[3], h_off[4]);
    launch_pass1<12, 4>(img1, img2, h_off[4], 0);

    k_pass2_all<<<NB2CUM(5), 128>>>();
    k_pass3_all<<<NB3CUM(5), 128>>>();
    k_final<<<1, 1>>>((float*)d_out);
}

// round 16
// speedup vs baseline: 1.3423x; 1.0235x over previous
#include <cuda_runtime.h>
#include <cuda_fp16.h>
#include <math.h>

#define WSZ 11

constexpr float CWAH[WSZ] = {
    0.00102838f, 0.00759875f, 0.03600080f, 0.10936069f, 0.21300554f,
    0.26601173f, 0.21300554f, 0.10936069f, 0.03600080f, 0.00759875f,
    0.00102838f};

// ---- compile-time float<->half converters ----------------------------------
__host__ __device__ constexpr unsigned short F2H(float f) {
    unsigned u = __builtin_bit_cast(unsigned int, f);
    unsigned sign = (u >> 16) & 0x8000u;
    int exp = (int)((u >> 23) & 0xffu) - 127 + 15;
    unsigned man = u & 0x7fffffu;
    unsigned base = ((unsigned)exp << 10) | (man >> 13);
    unsigned rem = man & 0x1fffu;
    if (rem > 0x1000u || (rem == 0x1000u && (base & 1u))) base++;
    return (unsigned short)(sign | base);
}
__host__ __device__ constexpr float H2F(unsigned short h) {
    int e = (h >> 10) & 31;
    unsigned m = h & 1023u;
    float f = 1.0f + (float)m / 1024.0f;
    int k = e - 15;
    while (k > 0) { f *= 2.0f; k--; }
    while (k < 0) { f *= 0.5f; k++; }
    return f;
}
__host__ __device__ constexpr unsigned HSPLAT(float f) {
    unsigned short h = F2H(f);
    return ((unsigned)h << 16) | h;
}
__host__ __device__ constexpr float SHSUM() {
    float s = 0.f;
    for (int i = 0; i < WSZ; i++) s += H2F(F2H(CWAH[i]));
    return s;
}
__host__ __device__ constexpr float SH3F() { float s = SHSUM(); return s * s * s; }
__host__ __device__ constexpr float SH6F() { float s = SH3F(); return s * s; }
__device__ constexpr float SC2 = SH3F();
__device__ constexpr float SC1 = SH6F();
__device__ constexpr unsigned CWH[WSZ] = {
    HSPLAT(CWAH[0]), HSPLAT(CWAH[1]), HSPLAT(CWAH[2]), HSPLAT(CWAH[3]),
    HSPLAT(CWAH[4]), HSPLAT(CWAH[5]), HSPLAT(CWAH[6]), HSPLAT(CWAH[7]),
    HSPLAT(CWAH[8]), HSPLAT(CWAH[9]), HSPLAT(CWAH[10])};

// ---- level geometry (constexpr) ---------------------------------------------
__host__ __device__ constexpr int  LSV(int l) {
    return l == 0 ? 192 : l == 1 ? 96 : l == 2 ? 48 : l == 3 ? 24 : 12;
}
__host__ __device__ constexpr int  WPC(int S) { return ((S - 10) + 3) & ~3; }
__host__ __device__ constexpr long S1SZC(int S) { return 10L * S * S * WPC(S); }
__host__ __device__ constexpr long S2SZC(int S) { return 10L * S * (S - 10) * WPC(S); }
__host__ __device__ constexpr long S1OFF(int l) {
    long o = 0; for (int i = 0; i < l; i++) o += S1SZC(LSV(i)); return o;
}
__host__ __device__ constexpr long S2OFF(int l) {
    long o = 0; for (int i = 0; i < l; i++) o += S2SZC(LSV(i)); return o;
}
__host__ __device__ constexpr int TOT2C(int S) {
    int Wo = S - 10, NQ = WPC(S) / 4, NHT = (Wo + 11) / 12;
    return 10 * S * NHT * NQ;
}
__host__ __device__ constexpr int NB2C(int S) { return (TOT2C(S) + 127) / 128; }
__host__ __device__ constexpr int NB2CUM(int l) {
    int s = 0; for (int i = 0; i < l; i++) s += NB2C(LSV(i)); return s;
}
__host__ __device__ constexpr int TOT3C(int S) {
    int Wo = S - 10, NDT = (Wo + 5) / 6, NQ2 = WPC(S) / 2;
    return 2 * NDT * Wo * NQ2;
}
__host__ __device__ constexpr int NB3C(int S) { return (TOT3C(S) + 127) / 128; }
__host__ __device__ constexpr int NB3CUM(int l) {
    int s = 0; for (int i = 0; i < l; i++) s += NB3C(LSV(i)); return s;
}
// pyramid offsets: level l data base in g_p1/g_p2
__host__ __device__ constexpr long POFFC(int l) {
    return l <= 1 ? 0 : l == 2 ? 1769472 : l == 3 ? 1990656 : 2018304;
}
// pass1_small_all cumulative blocks (levels 1..4)
__host__ __device__ constexpr int NB1S(int l) {   // blocks for level l
    int S = LSV(l); return 2 * (S / 2) * (S / 2);
}
__host__ __device__ constexpr int NB1CUM(int l) { // cum over levels 1..l
    int s = 0; for (int i = 1; i <= l; i++) s += NB1S(i); return s;
}

__device__ __forceinline__ __half2 u2h2(unsigned u) { return *(__half2*)&u; }
__device__ __forceinline__ __half2 mkpair(__half2 a, __half2 b) {
    return __halves2half2(__high2half(a), __low2half(b));
}

// ---------------- static device state (no allocations allowed) --------------
__device__ double g_ssim_sum[5];
__device__ double g_cs_sum[5];
__device__ int    g_fmax[5];
__device__ int    g_fmin[5];

__device__ __half g_s1[S1OFF(5)];
__device__ __half g_s2[S2OFF(5)];
__device__ float g_p1[2021760];
__device__ float g_p2[2021760];

// ---------------------------------------------------------------------------
__global__ void k_init() {
    int t = threadIdx.x;
    if (t < 5) {
        g_ssim_sum[t] = 0.0;
        g_cs_sum[t]   = 0.0;
        g_fmax[t]     = 0;
        g_fmin[t]     = 0;
    }
}

// ------------- pass 1 body: W-conv (half2) + flags (+pool if level 0) -------
template <int S, int LVL, int BT, bool DOPOOL>
__device__ __forceinline__ void pass1_body(const float* __restrict__ i1g,
                                           const float* __restrict__ i2g,
                                           int bid, __half* s1h, __half* s2h,
                                           int* sflp) {
    constexpr int  WP  = WPC(S);
    constexpr int  WP4 = WP / 4;
    constexpr int  SP  = S + 8;
    constexpr int  T   = S / 2;
    constexpr long FSZ = 2L * S * S * WP;
    constexpr long S1B = S1OFF(LVL);

    const float* i1 = (LVL == 0) ? i1g : (g_p1 + POFFC(LVL));
    const float* i2 = (LVL == 0) ? i2g : (g_p2 + POFFC(LVL));

    const int tid = threadIdx.x;
    int hp  = bid % (S / 2);
    int t0  = bid / (S / 2);
    int dp  = t0 % (S / 2);
    int b   = t0 / (S / 2);
    if (tid == 0) *sflp = 0;

    bool mx = false, mn = false;
    for (int idx = tid; idx < 4 * SP; idx += BT) {
        int r  = idx / SP, ii = idx - r * SP;
        int d  = 2 * dp + (r >> 1);
        int h  = 2 * hp + (r & 1);
        float v1 = 0.f, v2 = 0.f;
        if (ii < S) {
            long gb = (((long)b * S + d) * S + h) * S + ii;
            v1 = i1[gb];
            v2 = i2[gb];
        }
        s1h[idx] = __float2half(v1);
        s2h[idx] = __float2half(v2);
        mx |= (v1 > 128.0f);
        mn |= (v1 < -0.5f);
    }
    __syncthreads();
    if (mx | mn) atomicOr(sflp, (mx ? 1 : 0) | (mn ? 2 : 0));

    for (int task = tid; task < 4 * WP4; task += BT) {
        int r = task / WP4, q = task - r * WP4;
        int d = 2 * dp + (r >> 1);
        int h = 2 * hp + (r & 1);

        __half2 ax[8], ay[8];
        {
            const uint2* p1 = (const uint2*)&s1h[r * SP + 4 * q];
            const uint2* p2 = (const uint2*)&s2h[r * SP + 4 * q];
#pragma unroll
            for (int m = 0; m < 4; m++) {
                uint2 u1 = p1[m], u2 = p2[m];
                ax[2 * m]     = *(__half2*)&u1.x;
                ax[2 * m + 1] = *(__half2*)&u1.y;
                ay[2 * m]     = *(__half2*)&u2.x;
                ay[2 * m + 1] = *(__half2*)&u2.y;
            }
        }
        __half2 mxp[6], myp[6];
#pragma unroll
        for (int i = 0; i < 6; i++) {
            mxp[i] = mkpair(ax[i], ax[i + 1]);
            myp[i] = mkpair(ay[i], ay[i + 1]);
        }
        __half2 axx[7], ayy[7], axy[7], mxx[6], myy[6], mxy[6];
#pragma unroll
        for (int i = 0; i < 7; i++) {
            axx[i] = __hmul2(ax[i], ax[i]);
            ayy[i] = __hmul2(ay[i], ay[i]);
            axy[i] = __hmul2(ax[i], ay[i]);
        }
#pragma unroll
        for (int i = 0; i < 6; i++) {
            mxx[i] = __hmul2(mxp[i], mxp[i]);
            myy[i] = __hmul2(myp[i], myp[i]);
            mxy[i] = __hmul2(mxp[i], myp[i]);
        }

        uint2 o1v, o2v, o3v, o4v, o5v;
        const __half2 z = __float2half2_rn(0.f);
#pragma unroll
        for (int j = 0; j < 2; j++) {
            __half2 A1 = z, A2 = z, B1 = z, B2 = z, B3 = z;
#pragma unroll
            for (int k = 0; k < WSZ; k++) {
                __half2 w = u2h2(CWH[k]);
                if ((k & 1) == 0) {
                    int i = j + (k >> 1);
                    A1 = __hfma2(w, ax[i],  A1);
                    A2 = __hfma2(w, ay[i],  A2);
                    B1 = __hfma2(w, axx[i], B1);
                    B2 = __hfma2(w, ayy[i], B2);
                    B3 = __hfma2(w, axy[i], B3);
                } else {
                    int i = j + ((k - 1) >> 1);
                    A1 = __hfma2(w, mxp[i], A1);
                    A2 = __hfma2(w, myp[i], A2);
                    B1 = __hfma2(w, mxx[i], B1);
                    B2 = __hfma2(w, myy[i], B2);
                    B3 = __hfma2(w, mxy[i], B3);
                }
            }
            unsigned* dst1 = (j == 0) ? &o1v.x : &o1v.y;
            unsigned* dst2 = (j == 0) ? &o2v.x : &o2v.y;
            unsigned* dst3 = (j == 0) ? &o3v.x : &o3v.y;
            unsigned* dst4 = (j == 0) ? &o4v.x : &o4v.y;
            unsigned* dst5 = (j == 0) ? &o5v.x : &o5v.y;
            *dst1 = *(unsigned*)&A1;
            *dst2 = *(unsigned*)&A2;
            *dst3 = *(unsigned*)&B1;
            *dst4 = *(unsigned*)&B2;
            *dst5 = *(unsigned*)&B3;
        }
        long grow = ((long)b * S + d) * S + h;
        long o    = S1B + grow * WP + 4 * q;
        *(uint2*)&g_s1[o]           = o1v;
        *(uint2*)&g_s1[FSZ + o]     = o2v;
        *(uint2*)&g_s1[2 * FSZ + o] = o3v;
        *(uint2*)&g_s1[3 * FSZ + o] = o4v;
        *(uint2*)&g_s1[4 * FSZ + o] = o5v;
    }

    if (DOPOOL) {
        float* o1 = g_p1 + POFFC(LVL + 1);
        float* o2 = g_p2 + POFFC(LVL + 1);
        long orow = (((long)b * T + dp) * T + hp) * T;
        for (int x = tid; x < T; x += BT) {
            float r1 = 0.f, r2 = 0.f;
#pragma unroll
            for (int r = 0; r < 4; r++) {
                float2 a = __half22float2(*(const __half2*)&s1h[r * SP + 2 * x]);
                float2 c = __half22float2(*(const __half2*)&s2h[r * SP + 2 * x]);
                r1 += a.x + a.y;
                r2 += c.x + c.y;
            }
            o1[orow + x] = r1 * 0.125f;
            o2[orow + x] = r2 * 0.125f;
        }
    }

    __syncthreads();
    if (tid == 0 && *sflp) {
        int f = *sflp;
        if ((f & 1) && !g_fmax[LVL]) atomicOr(&g_fmax[LVL], 1);
        if ((f & 2) && !g_fmin[LVL]) atomicOr(&g_fmin[LVL], 1);
    }
}

// level 0 pass1 (writes level-1 pyramid)
__global__ void k_pass1_main(const float* __restrict__ i1,
                             const float* __restrict__ i2) {
    __shared__ __half s1h[4 * 200];
    __shared__ __half s2h[4 * 200];
    __shared__ int    sfl;
    pass1_body<192, 0, 184, true>(i1, i2, blockIdx.x, s1h, s2h, &sfl);
}

// levels 1-4 pass1 combined (pools already done by k_pool_all)
__global__ void k_pass1_small_all() {
    __shared__ __half s1h[4 * 104];
    __shared__ __half s2h[4 * 104];
    __shared__ int    sfl;
    int b = blockIdx.x;
    if (b < NB1CUM(1))
        pass1_body<96, 1, 96, false>(nullptr, nullptr, b, s1h, s2h, &sfl);
    else if (b < NB1CUM(2))
        pass1_body<48, 2, 96, false>(nullptr, nullptr, b - NB1CUM(1), s1h, s2h, &sfl);
    else if (b < NB1CUM(3))
        pass1_body<24, 3, 96, false>(nullptr, nullptr, b - NB1CUM(2), s1h, s2h, &sfl);
    else
        pass1_body<12, 4, 96, false>(nullptr, nullptr, b - NB1CUM(3), s1h, s2h, &sfl);
}

// ------------- pool levels 2..4 from level-1 pyramid (hierarchical) ---------
__global__ void k_pool_all() {
    // block covers a 16^3 region of level-1; grid = 2 * 6^3 = 432
    int blk = blockIdx.x;
    int b   = blk / 216;
    int r   = blk % 216;
    int cz  = r / 36, cy = (r / 6) % 6, cx = r % 6;
    int tid = threadIdx.x;

    __shared__ float sl1[576], sl2[576];   // 512 L2-cells + 64 L3-cells

    const float* p1 = g_p1 + POFFC(1);
    const float* p2 = g_p2 + POFFC(1);
    float* q21 = g_p1 + POFFC(2); float* q22 = g_p2 + POFFC(2);
    float* q31 = g_p1 + POFFC(3); float* q32 = g_p2 + POFFC(3);
    float* q41 = g_p1 + POFFC(4); float* q42 = g_p2 + POFFC(4);

    // level 2: 8^3 = 512 cells per block
    for (int c = tid; c < 512; c += 256) {
        int z = c >> 6, y = (c >> 3) & 7, x = c & 7;
        int gz = cz * 8 + z, gy = cy * 8 + y, gx = cx * 8 + x;
        float a1 = 0.f, a2 = 0.f;
#pragma unroll
        for (int dz = 0; dz < 2; dz++)
#pragma unroll
            for (int dy = 0; dy < 2; dy++) {
                long o = ((long)(b * 96 + 2 * gz + dz) * 96 + 2 * gy + dy) * 96 + 2 * gx;
                float2 v1 = *(const float2*)(p1 + o);
                float2 v2 = *(const float2*)(p2 + o);
                a1 += v1.x + v1.y;
                a2 += v2.x + v2.y;
            }
        a1 *= 0.125f; a2 *= 0.125f;
        sl1[c] = a1; sl2[c] = a2;
        long oo = ((long)(b * 48 + gz) * 48 + gy) * 48 + gx;
        q21[oo] = a1; q22[oo] = a2;
    }
    __syncthreads();

    // level 3: 4^3 = 64 cells
    if (tid < 64) {
        int z = tid >> 4, y = (tid >> 2) & 3, x = tid & 3;
        float a1 = 0.f, a2 = 0.f;
#pragma unroll
        for (int dz = 0; dz < 2; dz++)
#pragma unroll
            for (int dy = 0; dy < 2; dy++)
#pragma unroll
                for (int dx = 0; dx < 2; dx++) {
                    int i = ((2 * z + dz) << 6) + ((2 * y + dy) << 3) + 2 * x + dx;
                    a1 += sl1[i]; a2 += sl2[i];
                }
        a1 *= 0.125f; a2 *= 0.125f;
        sl1[512 + tid] = a1; sl2[512 + tid] = a2;
        long oo = ((long)(b * 24 + cz * 4 + z) * 24 + cy * 4 + y) * 24 + cx * 4 + x;
        q31[oo] = a1; q32[oo] = a2;
    }
    __syncthreads();

    // level 4: 2^3 = 8 cells
    if (tid < 8) {
        int z = tid >> 2, y = (tid >> 1) & 1, x = tid & 1;
        float a1 = 0.f, a2 = 0.f;
#pragma unroll
        for (int dz = 0; dz < 2; dz++)
#pragma unroll
            for (int dy = 0; dy < 2; dy++)
#pragma unroll
                for (int dx = 0; dx < 2; dx++) {
                    int i = 512 + ((2 * z + dz) << 4) + ((2 * y + dy) << 2) + 2 * x + dx;
                    a1 += sl1[i]; a2 += sl2[i];
                }
        a1 *= 0.125f; a2 *= 0.125f;
        long oo = ((long)(b * 12 + cz * 2 + z) * 12 + cy * 2 + y) * 12 + cx * 2 + x;
        q41[oo] = a1; q42[oo] = a2;
    }
}

// ------------- pass 2 body: H-conv, HFMA2, TH outputs per thread ------------
template <int S, int LVL>
__device__ __forceinline__ void pass2_body(int idx) {
    constexpr int Wo = S - 10, Ho = S - 10;
    constexpr int WP  = WPC(S);
    constexpr int NQ  = WP / 4;
    constexpr int TH  = 12;
    constexpr int NHT = (Ho + TH - 1) / TH;
    constexpr int TOT = TOT2C(S);
    constexpr long S1B = S1OFF(LVL);
    constexpr long S2B = S2OFF(LVL);

    if (idx >= TOT) return;
    int quad = idx % NQ;
    int t    = idx / NQ;
    int ht   = t % NHT;
    int q    = t / NHT;
    int ho0  = ht * TH;

    const __half* in = g_s1 + S1B + (long)q * S * WP + quad * 4;
    __half2 accA[TH], accB[TH];
    const __half2 z = __float2half2_rn(0.f);
#pragma unroll
    for (int j = 0; j < TH; j++) { accA[j] = z; accB[j] = z; }

#pragma unroll
    for (int k = 0; k < TH + 10; k++) {
        int h = ho0 + k;
        if (h < S) {
            uint2 u = *(const uint2*)(in + (long)h * WP);
            __half2 vA = *(__half2*)&u.x;
            __half2 vB = *(__half2*)&u.y;
#pragma unroll
            for (int j = 0; j < TH; j++) {
                int tt = k - j;
                if (tt >= 0 && tt < WSZ) {
                    __half2 w = u2h2(CWH[tt]);
                    accA[j] = __hfma2(w, vA, accA[j]);
                    accB[j] = __hfma2(w, vB, accB[j]);
                }
            }
        }
    }
    __half* out = g_s2 + S2B + (long)q * Ho * WP + quad * 4;
#pragma unroll
    for (int j = 0; j < TH; j++) {
        int ho = ho0 + j;
        if (ho < Ho) {
            uint2 u;
            u.x = *(unsigned*)&accA[j];
            u.y = *(unsigned*)&accB[j];
            *(uint2*)(out + (long)ho * WP) = u;
        }
    }
}

__global__ void k_pass2_all() {
    int b   = blockIdx.x;
    int tid = threadIdx.x;
    if (b < NB2CUM(1))      pass2_body<192, 0>((b - NB2CUM(0)) * 128 + tid);
    else if (b < NB2CUM(2)) pass2_body<96, 1>((b - NB2CUM(1)) * 128 + tid);
    else if (b < NB2CUM(3)) pass2_body<48, 2>((b - NB2CUM(2)) * 128 + tid);
    else if (b < NB2CUM(4)) pass2_body<24, 3>((b - NB2CUM(3)) * 128 + tid);
    else                    pass2_body<12, 4>((b - NB2CUM(4)) * 128 + tid);
}

// ------------- pass 3 body: D-conv (HFMA2) + SSIM/CS (fp32) + reduction -----
__device__ __forceinline__ float warp_sum(float v) {
#pragma unroll
    for (int o = 16; o; o >>= 1) v += __shfl_down_sync(0xffffffffu, v, o);
    return v;
}

template <int S, int LVL>
__device__ __forceinline__ void pass3_body(int idx) {
    constexpr int  Wo  = S - 10, Ho = Wo, Do = Wo;
    constexpr int  WP  = WPC(S);
    constexpr int  NQ2 = WP / 2;
    constexpr int  TD  = 6;
    constexpr int  NDT = (Do + TD - 1) / TD;
    constexpr long HWP = (long)Ho * WP;
    constexpr long FST = 2L * S * HWP;
    constexpr int  TOT = TOT3C(S);
    constexpr long S2B = S2OFF(LVL);

    float sum_s = 0.f, sum_c = 0.f;
    if (idx < TOT) {
        int p  = idx % NQ2;
        int t  = idx / NQ2;
        int ho = t % Ho;
        int t2 = t / Ho;
        int dt = t2 % NDT;
        int b  = t2 / NDT;
        int d0 = dt * TD;

        const __half* base = g_s2 + S2B + (long)b * S * HWP + (long)ho * WP + 2 * p;
        __half2 A0[TD], A1[TD], A2[TD], A3[TD], A4[TD];
        const __half2 z = __float2half2_rn(0.f);
#pragma unroll
        for (int j = 0; j < TD; j++) { A0[j] = A1[j] = A2[j] = A3[j] = A4[j] = z; }
#pragma unroll
        for (int k = 0; k < TD + 10; k++) {
            int d = d0 + k;
            if (d < S) {
                const __half* pp = base + (long)d * HWP;
                __half2 v0 = *(const __half2*)(pp);
                __half2 v1 = *(const __half2*)(pp + FST);
                __half2 v2 = *(const __half2*)(pp + 2 * FST);
                __half2 v3 = *(const __half2*)(pp + 3 * FST);
                __half2 v4 = *(const __half2*)(pp + 4 * FST);
#pragma unroll
                for (int j = 0; j < TD; j++) {
                    int tt = k - j;
                    if (tt >= 0 && tt < WSZ) {
                        __half2 w = u2h2(CWH[tt]);
                        A0[j] = __hfma2(w, v0, A0[j]);
                        A1[j] = __hfma2(w, v1, A1[j]);
                        A2[j] = __hfma2(w, v2, A2[j]);
                        A3[j] = __hfma2(w, v3, A3[j]);
                        A4[j] = __hfma2(w, v4, A4[j]);
                    }
                }
            }
        }
        float maxv = g_fmax[LVL] ? 255.0f : 1.0f;
        float minv = g_fmin[LVL] ? -1.0f : 0.0f;
        float L  = maxv - minv;
        float C1 = (0.01f * L) * (0.01f * L) * SC1;
        float C2 = (0.03f * L) * (0.03f * L) * SC2;
        bool lane0 = (2 * p) < Wo;
        bool lane1 = (2 * p + 1) < Wo;
#pragma unroll
        for (int j = 0; j < TD; j++) {
            if (d0 + j < Do) {
                float2 m1 = __half22float2(A0[j]);
                float2 m2 = __half22float2(A1[j]);
                float2 q1 = __half22float2(A2[j]);
                float2 q2 = __half22float2(A3[j]);
                float2 q3 = __half22float2(A4[j]);
                if (lane0) {
                    float mu1 = m1.x, mu2 = m2.x;
                    float v1 = 2.0f * (q3.x - mu1 * mu2) + C2;
                    float v2 = (q1.x - mu1 * mu1) + (q2.x - mu2 * mu2) + C2;
                    sum_c += v1 / v2;
                    sum_s += (2.0f * mu1 * mu2 + C1) * v1 /
                             ((mu1 * mu1 + mu2 * mu2 + C1) * v2);
                }
                if (lane1) {
                    float mu1 = m1.y, mu2 = m2.y;
                    float v1 = 2.0f * (q3.y - mu1 * mu2) + C2;
                    float v2 = (q1.y - mu1 * mu1) + (q2.y - mu2 * mu2) + C2;
                    sum_c += v1 / v2;
                    sum_s += (2.0f * mu1 * mu2 + C1) * v1 /
                             ((mu1 * mu1 + mu2 * mu2 + C1) * v2);
                }
            }
        }
    }
    sum_c = warp_sum(sum_c);
    sum_s = warp_sum(sum_s);
    __shared__ float shc[4], shs[4];
    int lane = threadIdx.x & 31, wid = threadIdx.x >> 5;
    if (lane == 0) { shc[wid] = sum_c; shs[wid] = sum_s; }
    __syncthreads();
    if (threadIdx.x == 0) {
        float tc = shc[0] + shc[1] + shc[2] + shc[3];
        float ts = shs[0] + shs[1] + shs[2] + shs[3];
        atomicAdd(&g_cs_sum[LVL],   (double)tc);
        atomicAdd(&g_ssim_sum[LVL], (double)ts);
    }
}

__global__ void k_pass3_all() {
    int b   = blockIdx.x;
    int tid = threadIdx.x;
    if (b < NB3CUM(1))      pass3_body<192, 0>((b - NB3CUM(0)) * 128 + tid);
    else if (b < NB3CUM(2)) pass3_body<96, 1>((b - NB3CUM(1)) * 128 + tid);
    else if (b < NB3CUM(3)) pass3_body<48, 2>((b - NB3CUM(2)) * 128 + tid);
    else if (b < NB3CUM(4)) pass3_body<24, 3>((b - NB3CUM(3)) * 128 + tid);
    else                    pass3_body<12, 4>((b - NB3CUM(4)) * 128 + tid);
}

// ------------- final combine -------------------------------------------------
__global__ void k_final(float* out) {
    const double W[5]   = {0.0448, 0.2856, 0.3001, 0.2363, 0.1333};
    const double cnt[5] = {12057136.0, 1272112.0, 109744.0, 5488.0, 16.0};
    double p = 1.0;
    for (int l = 0; l < 4; l++) p *= pow(g_cs_sum[l] / cnt[l], W[l]);
    p *= pow(g_ssim_sum[4] / cnt[4], W[4]);
    out[0] = (float)p;
}

// ---------------------------------------------------------------------------
extern "C" void kernel_launch(void* const* d_in, const int* in_sizes, int n_in,
                              void* d_out, int out_size) {
    const float* img1 = (const float*)d_in[0];
    const float* img2 = (const float*)d_in[1];

    k_init<<<1, 32>>>();
    k_pass1_main<<<2 * 96 * 96, 184>>>(img1, img2);
    k_pool_all<<<432, 256>>>();
    k_pass1_small_all<<<NB1CUM(4), 96>>>();
    k_pass2_all<<<NB2CUM(5), 128>>>();
    k_pass3_all<<<NB3CUM(5), 128>>>();
    k_final<<<1, 1>>>((float*)d_out);
}

// round 17
// speedup vs baseline: 1.3524x; 1.0075x over previous
#include <cuda_runtime.h>
#include <cuda_fp16.h>
#include <math.h>

#define WSZ 11

constexpr float CWAH[WSZ] = {
    0.00102838f, 0.00759875f, 0.03600080f, 0.10936069f, 0.21300554f,
    0.26601173f, 0.21300554f, 0.10936069f, 0.03600080f, 0.00759875f,
    0.00102838f};

// ---- compile-time float<->half converters ----------------------------------
__host__ __device__ constexpr unsigned short F2H(float f) {
    unsigned u = __builtin_bit_cast(unsigned int, f);
    unsigned sign = (u >> 16) & 0x8000u;
    int exp = (int)((u >> 23) & 0xffu) - 127 + 15;
    unsigned man = u & 0x7fffffu;
    unsigned base = ((unsigned)exp << 10) | (man >> 13);
    unsigned rem = man & 0x1fffu;
    if (rem > 0x1000u || (rem == 0x1000u && (base & 1u))) base++;
    return (unsigned short)(sign | base);
}
__host__ __device__ constexpr float H2F(unsigned short h) {
    int e = (h >> 10) & 31;
    unsigned m = h & 1023u;
    float f = 1.0f + (float)m / 1024.0f;
    int k = e - 15;
    while (k > 0) { f *= 2.0f; k--; }
    while (k < 0) { f *= 0.5f; k++; }
    return f;
}
__host__ __device__ constexpr unsigned HSPLAT(float f) {
    unsigned short h = F2H(f);
    return ((unsigned)h << 16) | h;
}
__host__ __device__ constexpr float SHSUM() {
    float s = 0.f;
    for (int i = 0; i < WSZ; i++) s += H2F(F2H(CWAH[i]));
    return s;
}
__host__ __device__ constexpr float SH3F() { float s = SHSUM(); return s * s * s; }
__host__ __device__ constexpr float SH6F() { float s = SH3F(); return s * s; }
__device__ constexpr float SC2 = SH3F();
__device__ constexpr float SC1 = SH6F();
__device__ constexpr unsigned CWH[WSZ] = {
    HSPLAT(CWAH[0]), HSPLAT(CWAH[1]), HSPLAT(CWAH[2]), HSPLAT(CWAH[3]),
    HSPLAT(CWAH[4]), HSPLAT(CWAH[5]), HSPLAT(CWAH[6]), HSPLAT(CWAH[7]),
    HSPLAT(CWAH[8]), HSPLAT(CWAH[9]), HSPLAT(CWAH[10])};

// ---- level geometry (constexpr) ---------------------------------------------
__host__ __device__ constexpr int  LSV(int l) {
    return l == 0 ? 192 : l == 1 ? 96 : l == 2 ? 48 : l == 3 ? 24 : 12;
}
__host__ __device__ constexpr int  WPC(int S) { return ((S - 10) + 3) & ~3; }
__host__ __device__ constexpr long S1SZC(int S) { return 10L * S * S * WPC(S); }
__host__ __device__ constexpr long S2SZC(int S) { return 10L * S * (S - 10) * WPC(S); }
__host__ __device__ constexpr long S1OFF(int l) {
    long o = 0; for (int i = 0; i < l; i++) o += S1SZC(LSV(i)); return o;
}
__host__ __device__ constexpr long S2OFF(int l) {
    long o = 0; for (int i = 0; i < l; i++) o += S2SZC(LSV(i)); return o;
}
__host__ __device__ constexpr int TOT2C(int S) {
    int Wo = S - 10, NQ = WPC(S) / 4, NHT = (Wo + 11) / 12;
    return 10 * S * NHT * NQ;
}
__host__ __device__ constexpr int NB2C(int S) { return (TOT2C(S) + 127) / 128; }
__host__ __device__ constexpr int TOT3C(int S) {
    int Wo = S - 10, NDT = (Wo + 5) / 6, NQ2 = WPC(S) / 2;
    return 2 * NDT * Wo * NQ2;
}
__host__ __device__ constexpr int NB3C(int S) { return (TOT3C(S) + 127) / 128; }
// small-level cumulative blocks (levels 1..4)
__host__ __device__ constexpr int NB2SCUM(int l) {  // cum over levels 1..l
    int s = 0; for (int i = 1; i <= l; i++) s += NB2C(LSV(i)); return s;
}
__host__ __device__ constexpr int NB3SCUM(int l) {
    int s = 0; for (int i = 1; i <= l; i++) s += NB3C(LSV(i)); return s;
}
// pyramid offsets: level l data base in g_p1/g_p2
__host__ __device__ constexpr long POFFC(int l) {
    return l <= 1 ? 0 : l == 2 ? 1769472 : l == 3 ? 1990656 : 2018304;
}
// pass1 small cumulative blocks (levels 1..4)
__host__ __device__ constexpr int NB1S(int l) {
    int S = LSV(l); return 2 * (S / 2) * (S / 2);
}
__host__ __device__ constexpr int NB1CUM(int l) {
    int s = 0; for (int i = 1; i <= l; i++) s += NB1S(i); return s;
}

__device__ __forceinline__ __half2 u2h2(unsigned u) { return *(__half2*)&u; }
__device__ __forceinline__ __half2 mkpair(__half2 a, __half2 b) {
    return __halves2half2(__high2half(a), __low2half(b));
}

// ---------------- static device state (no allocations allowed) --------------
__device__ double g_ssim_sum[5];
__device__ double g_cs_sum[5];
__device__ int    g_fmax[5];
__device__ int    g_fmin[5];

__device__ __half g_s1[S1OFF(5)];
__device__ __half g_s2[S2OFF(5)];
__device__ float g_p1[2021760];
__device__ float g_p2[2021760];

// ---------------------------------------------------------------------------
__global__ void k_init() {
    int t = threadIdx.x;
    if (t < 5) {
        g_ssim_sum[t] = 0.0;
        g_cs_sum[t]   = 0.0;
        g_fmax[t]     = 0;
        g_fmin[t]     = 0;
    }
}

// ------------- pass 1 body: W-conv (half2) + flags (+pool if level 0) -------
template <int S, int LVL, int BT, bool DOPOOL>
__device__ __forceinline__ void pass1_body(const float* __restrict__ i1g,
                                           const float* __restrict__ i2g,
                                           int bid, __half* s1h, __half* s2h,
                                           int* sflp) {
    constexpr int  WP  = WPC(S);
    constexpr int  WP4 = WP / 4;
    constexpr int  SP  = S + 8;
    constexpr int  T   = S / 2;
    constexpr long FSZ = 2L * S * S * WP;
    constexpr long S1B = S1OFF(LVL);

    const float* i1 = (LVL == 0) ? i1g : (g_p1 + POFFC(LVL));
    const float* i2 = (LVL == 0) ? i2g : (g_p2 + POFFC(LVL));

    const int tid = threadIdx.x;
    int hp  = bid % (S / 2);
    int t0  = bid / (S / 2);
    int dp  = t0 % (S / 2);
    int b   = t0 / (S / 2);
    if (tid == 0) *sflp = 0;

    bool mx = false, mn = false;
    for (int idx = tid; idx < 4 * SP; idx += BT) {
        int r  = idx / SP, ii = idx - r * SP;
        int d  = 2 * dp + (r >> 1);
        int h  = 2 * hp + (r & 1);
        float v1 = 0.f, v2 = 0.f;
        if (ii < S) {
            long gb = (((long)b * S + d) * S + h) * S + ii;
            v1 = i1[gb];
            v2 = i2[gb];
        }
        s1h[idx] = __float2half(v1);
        s2h[idx] = __float2half(v2);
        mx |= (v1 > 128.0f);
        mn |= (v1 < -0.5f);
    }
    __syncthreads();
    if (mx | mn) atomicOr(sflp, (mx ? 1 : 0) | (mn ? 2 : 0));

    for (int task = tid; task < 4 * WP4; task += BT) {
        int r = task / WP4, q = task - r * WP4;
        int d = 2 * dp + (r >> 1);
        int h = 2 * hp + (r & 1);

        __half2 ax[8], ay[8];
        {
            const uint2* p1 = (const uint2*)&s1h[r * SP + 4 * q];
            const uint2* p2 = (const uint2*)&s2h[r * SP + 4 * q];
#pragma unroll
            for (int m = 0; m < 4; m++) {
                uint2 u1 = p1[m], u2 = p2[m];
                ax[2 * m]     = *(__half2*)&u1.x;
                ax[2 * m + 1] = *(__half2*)&u1.y;
                ay[2 * m]     = *(__half2*)&u2.x;
                ay[2 * m + 1] = *(__half2*)&u2.y;
            }
        }
        __half2 mxp[6], myp[6];
#pragma unroll
        for (int i = 0; i < 6; i++) {
            mxp[i] = mkpair(ax[i], ax[i + 1]);
            myp[i] = mkpair(ay[i], ay[i + 1]);
        }
        __half2 axx[7], ayy[7], axy[7], mxx[6], myy[6], mxy[6];
#pragma unroll
        for (int i = 0; i < 7; i++) {
            axx[i] = __hmul2(ax[i], ax[i]);
            ayy[i] = __hmul2(ay[i], ay[i]);
            axy[i] = __hmul2(ax[i], ay[i]);
        }
#pragma unroll
        for (int i = 0; i < 6; i++) {
            mxx[i] = __hmul2(mxp[i], mxp[i]);
            myy[i] = __hmul2(myp[i], myp[i]);
            mxy[i] = __hmul2(mxp[i], myp[i]);
        }

        uint2 o1v, o2v, o3v, o4v, o5v;
        const __half2 z = __float2half2_rn(0.f);
#pragma unroll
        for (int j = 0; j < 2; j++) {
            __half2 A1 = z, A2 = z, B1 = z, B2 = z, B3 = z;
#pragma unroll
            for (int k = 0; k < WSZ; k++) {
                __half2 w = u2h2(CWH[k]);
                if ((k & 1) == 0) {
                    int i = j + (k >> 1);
                    A1 = __hfma2(w, ax[i],  A1);
                    A2 = __hfma2(w, ay[i],  A2);
                    B1 = __hfma2(w, axx[i], B1);
                    B2 = __hfma2(w, ayy[i], B2);
                    B3 = __hfma2(w, axy[i], B3);
                } else {
                    int i = j + ((k - 1) >> 1);
                    A1 = __hfma2(w, mxp[i], A1);
                    A2 = __hfma2(w, myp[i], A2);
                    B1 = __hfma2(w, mxx[i], B1);
                    B2 = __hfma2(w, myy[i], B2);
                    B3 = __hfma2(w, mxy[i], B3);
                }
            }
            unsigned* dst1 = (j == 0) ? &o1v.x : &o1v.y;
            unsigned* dst2 = (j == 0) ? &o2v.x : &o2v.y;
            unsigned* dst3 = (j == 0) ? &o3v.x : &o3v.y;
            unsigned* dst4 = (j == 0) ? &o4v.x : &o4v.y;
            unsigned* dst5 = (j == 0) ? &o5v.x : &o5v.y;
            *dst1 = *(unsigned*)&A1;
            *dst2 = *(unsigned*)&A2;
            *dst3 = *(unsigned*)&B1;
            *dst4 = *(unsigned*)&B2;
            *dst5 = *(unsigned*)&B3;
        }
        long grow = ((long)b * S + d) * S + h;
        long o    = S1B + grow * WP + 4 * q;
        *(uint2*)&g_s1[o]           = o1v;
        *(uint2*)&g_s1[FSZ + o]     = o2v;
        *(uint2*)&g_s1[2 * FSZ + o] = o3v;
        *(uint2*)&g_s1[3 * FSZ + o] = o4v;
        *(uint2*)&g_s1[4 * FSZ + o] = o5v;
    }

    if (DOPOOL) {
        float* o1 = g_p1 + POFFC(LVL + 1);
        float* o2 = g_p2 + POFFC(LVL + 1);
        long orow = (((long)b * T + dp) * T + hp) * T;
        for (int x = tid; x < T; x += BT) {
            float r1 = 0.f, r2 = 0.f;
#pragma unroll
            for (int r = 0; r < 4; r++) {
                float2 a = __half22float2(*(const __half2*)&s1h[r * SP + 2 * x]);
                float2 c = __half22float2(*(const __half2*)&s2h[r * SP + 2 * x]);
                r1 += a.x + a.y;
                r2 += c.x + c.y;
            }
            o1[orow + x] = r1 * 0.125f;
            o2[orow + x] = r2 * 0.125f;
        }
    }

    __syncthreads();
    if (tid == 0 && *sflp) {
        int f = *sflp;
        if ((f & 1) && !g_fmax[LVL]) atomicOr(&g_fmax[LVL], 1);
        if ((f & 2) && !g_fmin[LVL]) atomicOr(&g_fmin[LVL], 1);
    }
}

// level 0 pass1 (writes level-1 pyramid)
__global__ void k_pass1_main(const float* __restrict__ i1,
                             const float* __restrict__ i2) {
    __shared__ __half s1h[4 * 200];
    __shared__ __half s2h[4 * 200];
    __shared__ int    sfl;
    pass1_body<192, 0, 184, true>(i1, i2, blockIdx.x, s1h, s2h, &sfl);
}

// ------------- pool levels 2..4 from level-1 pyramid (hierarchical) ---------
__global__ void k_pool_all() {
    int blk = blockIdx.x;
    int b   = blk / 216;
    int r   = blk % 216;
    int cz  = r / 36, cy = (r / 6) % 6, cx = r % 6;
    int tid = threadIdx.x;

    __shared__ float sl1[576], sl2[576];

    const float* p1 = g_p1 + POFFC(1);
    const float* p2 = g_p2 + POFFC(1);
    float* q21 = g_p1 + POFFC(2); float* q22 = g_p2 + POFFC(2);
    float* q31 = g_p1 + POFFC(3); float* q32 = g_p2 + POFFC(3);
    float* q41 = g_p1 + POFFC(4); float* q42 = g_p2 + POFFC(4);

    for (int c = tid; c < 512; c += 256) {
        int z = c >> 6, y = (c >> 3) & 7, x = c & 7;
        int gz = cz * 8 + z, gy = cy * 8 + y, gx = cx * 8 + x;
        float a1 = 0.f, a2 = 0.f;
#pragma unroll
        for (int dz = 0; dz < 2; dz++)
#pragma unroll
            for (int dy = 0; dy < 2; dy++) {
                long o = ((long)(b * 96 + 2 * gz + dz) * 96 + 2 * gy + dy) * 96 + 2 * gx;
                float2 v1 = *(const float2*)(p1 + o);
                float2 v2 = *(const float2*)(p2 + o);
                a1 += v1.x + v1.y;
                a2 += v2.x + v2.y;
            }
        a1 *= 0.125f; a2 *= 0.125f;
        sl1[c] = a1; sl2[c] = a2;
        long oo = ((long)(b * 48 + gz) * 48 + gy) * 48 + gx;
        q21[oo] = a1; q22[oo] = a2;
    }
    __syncthreads();

    if (tid < 64) {
        int z = tid >> 4, y = (tid >> 2) & 3, x = tid & 3;
        float a1 = 0.f, a2 = 0.f;
#pragma unroll
        for (int dz = 0; dz < 2; dz++)
#pragma unroll
            for (int dy = 0; dy < 2; dy++)
#pragma unroll
                for (int dx = 0; dx < 2; dx++) {
                    int i = ((2 * z + dz) << 6) + ((2 * y + dy) << 3) + 2 * x + dx;
                    a1 += sl1[i]; a2 += sl2[i];
                }
        a1 *= 0.125f; a2 *= 0.125f;
        sl1[512 + tid] = a1; sl2[512 + tid] = a2;
        long oo = ((long)(b * 24 + cz * 4 + z) * 24 + cy * 4 + y) * 24 + cx * 4 + x;
        q31[oo] = a1; q32[oo] = a2;
    }
    __syncthreads();

    if (tid < 8) {
        int z = tid >> 2, y = (tid >> 1) & 1, x = tid & 1;
        float a1 = 0.f, a2 = 0.f;
#pragma unroll
        for (int dz = 0; dz < 2; dz++)
#pragma unroll
            for (int dy = 0; dy < 2; dy++)
#pragma unroll
                for (int dx = 0; dx < 2; dx++) {
                    int i = 512 + ((2 * z + dz) << 4) + ((2 * y + dy) << 2) + 2 * x + dx;
                    a1 += sl1[i]; a2 += sl2[i];
                }
        a1 *= 0.125f; a2 *= 0.125f;
        long oo = ((long)(b * 12 + cz * 2 + z) * 12 + cy * 2 + y) * 12 + cx * 2 + x;
        q41[oo] = a1; q42[oo] = a2;
    }
}

// ------------- pass 2 body: H-conv, HFMA2, TH outputs per thread ------------
template <int S, int LVL>
__device__ __forceinline__ void pass2_body(int idx) {
    constexpr int Wo = S - 10, Ho = S - 10;
    constexpr int WP  = WPC(S);
    constexpr int NQ  = WP / 4;
    constexpr int TH  = 12;
    constexpr int NHT = (Ho + TH - 1) / TH;
    constexpr int TOT = TOT2C(S);
    constexpr long S1B = S1OFF(LVL);
    constexpr long S2B = S2OFF(LVL);

    if (idx >= TOT) return;
    int quad = idx % NQ;
    int t    = idx / NQ;
    int ht   = t % NHT;
    int q    = t / NHT;
    int ho0  = ht * TH;

    const __half* in = g_s1 + S1B + (long)q * S * WP + quad * 4;
    __half2 accA[TH], accB[TH];
    const __half2 z = __float2half2_rn(0.f);
#pragma unroll
    for (int j = 0; j < TH; j++) { accA[j] = z; accB[j] = z; }

#pragma unroll
    for (int k = 0; k < TH + 10; k++) {
        int h = ho0 + k;
        if (h < S) {
            uint2 u = *(const uint2*)(in + (long)h * WP);
            __half2 vA = *(__half2*)&u.x;
            __half2 vB = *(__half2*)&u.y;
#pragma unroll
            for (int j = 0; j < TH; j++) {
                int tt = k - j;
                if (tt >= 0 && tt < WSZ) {
                    __half2 w = u2h2(CWH[tt]);
                    accA[j] = __hfma2(w, vA, accA[j]);
                    accB[j] = __hfma2(w, vB, accB[j]);
                }
            }
        }
    }
    __half* out = g_s2 + S2B + (long)q * Ho * WP + quad * 4;
#pragma unroll
    for (int j = 0; j < TH; j++) {
        int ho = ho0 + j;
        if (ho < Ho) {
            uint2 u;
            u.x = *(unsigned*)&accA[j];
            u.y = *(unsigned*)&accB[j];
            *(uint2*)(out + (long)ho * WP) = u;
        }
    }
}

// ------------- pass 3 body: D-conv (HFMA2) + SSIM/CS (fp32) + reduction -----
__device__ __forceinline__ float warp_sum(float v) {
#pragma unroll
    for (int o = 16; o; o >>= 1) v += __shfl_down_sync(0xffffffffu, v, o);
    return v;
}

template <int S, int LVL>
__device__ __forceinline__ void pass3_body(int idx) {
    constexpr int  Wo  = S - 10, Ho = Wo, Do = Wo;
    constexpr int  WP  = WPC(S);
    constexpr int  NQ2 = WP / 2;
    constexpr int  TD  = 6;
    constexpr int  NDT = (Do + TD - 1) / TD;
    constexpr long HWP = (long)Ho * WP;
    constexpr long FST = 2L * S * HWP;
    constexpr int  TOT = TOT3C(S);
    constexpr long S2B = S2OFF(LVL);

    float sum_s = 0.f, sum_c = 0.f;
    if (idx < TOT) {
        int p  = idx % NQ2;
        int t  = idx / NQ2;
        int ho = t % Ho;
        int t2 = t / Ho;
        int dt = t2 % NDT;
        int b  = t2 / NDT;
        int d0 = dt * TD;

        const __half* base = g_s2 + S2B + (long)b * S * HWP + (long)ho * WP + 2 * p;
        __half2 A0[TD], A1[TD], A2[TD], A3[TD], A4[TD];
        const __half2 z = __float2half2_rn(0.f);
#pragma unroll
        for (int j = 0; j < TD; j++) { A0[j] = A1[j] = A2[j] = A3[j] = A4[j] = z; }
#pragma unroll
        for (int k = 0; k < TD + 10; k++) {
            int d = d0 + k;
            if (d < S) {
                const __half* pp = base + (long)d * HWP;
                __half2 v0 = *(const __half2*)(pp);
                __half2 v1 = *(const __half2*)(pp + FST);
                __half2 v2 = *(const __half2*)(pp + 2 * FST);
                __half2 v3 = *(const __half2*)(pp + 3 * FST);
                __half2 v4 = *(const __half2*)(pp + 4 * FST);
#pragma unroll
                for (int j = 0; j < TD; j++) {
                    int tt = k - j;
                    if (tt >= 0 && tt < WSZ) {
                        __half2 w = u2h2(CWH[tt]);
                        A0[j] = __hfma2(w, v0, A0[j]);
                        A1[j] = __hfma2(w, v1, A1[j]);
                        A2[j] = __hfma2(w, v2, A2[j]);
                        A3[j] = __hfma2(w, v3, A3[j]);
                        A4[j] = __hfma2(w, v4, A4[j]);
                    }
                }
            }
        }
        float maxv = g_fmax[LVL] ? 255.0f : 1.0f;
        float minv = g_fmin[LVL] ? -1.0f : 0.0f;
        float L  = maxv - minv;
        float C1 = (0.01f * L) * (0.01f * L) * SC1;
        float C2 = (0.03f * L) * (0.03f * L) * SC2;
        bool lane0 = (2 * p) < Wo;
        bool lane1 = (2 * p + 1) < Wo;
#pragma unroll
        for (int j = 0; j < TD; j++) {
            if (d0 + j < Do) {
                float2 m1 = __half22float2(A0[j]);
                float2 m2 = __half22float2(A1[j]);
                float2 q1 = __half22float2(A2[j]);
                float2 q2 = __half22float2(A3[j]);
                float2 q3 = __half22float2(A4[j]);
                if (lane0) {
                    float mu1 = m1.x, mu2 = m2.x;
                    float v1 = 2.0f * (q3.x - mu1 * mu2) + C2;
                    float v2 = (q1.x - mu1 * mu1) + (q2.x - mu2 * mu2) + C2;
                    sum_c += v1 / v2;
                    sum_s += (2.0f * mu1 * mu2 + C1) * v1 /
                             ((mu1 * mu1 + mu2 * mu2 + C1) * v2);
                }
                if (lane1) {
                    float mu1 = m1.y, mu2 = m2.y;
                    float v1 = 2.0f * (q3.y - mu1 * mu2) + C2;
                    float v2 = (q1.y - mu1 * mu1) + (q2.y - mu2 * mu2) + C2;
                    sum_c += v1 / v2;
                    sum_s += (2.0f * mu1 * mu2 + C1) * v1 /
                             ((mu1 * mu1 + mu2 * mu2 + C1) * v2);
                }
            }
        }
    }
    sum_c = warp_sum(sum_c);
    sum_s = warp_sum(sum_s);
    __shared__ float shc[4], shs[4];
    int lane = threadIdx.x & 31, wid = threadIdx.x >> 5;
    if (lane == 0) { shc[wid] = sum_c; shs[wid] = sum_s; }
    __syncthreads();
    if (threadIdx.x == 0) {
        float tc = shc[0] + shc[1] + shc[2] + shc[3];
        float ts = shs[0] + shs[1] + shs[2] + shs[3];
        atomicAdd(&g_cs_sum[LVL],   (double)tc);
        atomicAdd(&g_ssim_sum[LVL], (double)ts);
    }
}

// ------------- fused launches ------------------------------------------------
// fuseA: pass2(level0) + pass1(levels 1-4)   [both ready after pool_all]
__global__ void k_fuseA() {
    int b   = blockIdx.x;
    int tid = threadIdx.x;
    if (b < NB2C(192)) {
        pass2_body<192, 0>(b * 128 + tid);
    } else {
        __shared__ __half s1h[4 * 104];
        __shared__ __half s2h[4 * 104];
        __shared__ int    sfl;
        int b2 = b - NB2C(192);
        if (b2 < NB1CUM(1))
            pass1_body<96, 1, 128, false>(nullptr, nullptr, b2, s1h, s2h, &sfl);
        else if (b2 < NB1CUM(2))
            pass1_body<48, 2, 128, false>(nullptr, nullptr, b2 - NB1CUM(1), s1h, s2h, &sfl);
        else if (b2 < NB1CUM(3))
            pass1_body<24, 3, 128, false>(nullptr, nullptr, b2 - NB1CUM(2), s1h, s2h, &sfl);
        else
            pass1_body<12, 4, 128, false>(nullptr, nullptr, b2 - NB1CUM(3), s1h, s2h, &sfl);
    }
}

// fuseB: pass3(level0) + pass2(levels 1-4)
__global__ void k_fuseB() {
    int b   = blockIdx.x;
    int tid = threadIdx.x;
    if (b < NB3C(192)) {
        pass3_body<192, 0>(b * 128 + tid);
    } else {
        int b2 = b - NB3C(192);
        if (b2 < NB2SCUM(1))      pass2_body<96, 1>(b2 * 128 + tid);
        else if (b2 < NB2SCUM(2)) pass2_body<48, 2>((b2 - NB2SCUM(1)) * 128 + tid);
        else if (b2 < NB2SCUM(3)) pass2_body<24, 3>((b2 - NB2SCUM(2)) * 128 + tid);
        else                      pass2_body<12, 4>((b2 - NB2SCUM(3)) * 128 + tid);
    }
}

// fuseC: pass3(levels 1-4)
__global__ void k_fuseC() {
    int b   = blockIdx.x;
    int tid = threadIdx.x;
    if (b < NB3SCUM(1))      pass3_body<96, 1>(b * 128 + tid);
    else if (b < NB3SCUM(2)) pass3_body<48, 2>((b - NB3SCUM(1)) * 128 + tid);
    else if (b < NB3SCUM(3)) pass3_body<24, 3>((b - NB3SCUM(2)) * 128 + tid);
    else                     pass3_body<12, 4>((b - NB3SCUM(3)) * 128 + tid);
}

// ------------- final combine -------------------------------------------------
__global__ void k_final(float* out) {
    const double W[5]   = {0.0448, 0.2856, 0.3001, 0.2363, 0.1333};
    const double cnt[5] = {12057136.0, 1272112.0, 109744.0, 5488.0, 16.0};
    double p = 1.0;
    for (int l = 0; l < 4; l++) p *= pow(g_cs_sum[l] / cnt[l], W[l]);
    p *= pow(g_ssim_sum[4] / cnt[4], W[4]);
    out[0] = (float)p;
}

// ---------------------------------------------------------------------------
extern "C" void kernel_launch(void* const* d_in, const int* in_sizes, int n_in,
                              void* d_out, int out_size) {
    const float* img1 = (const float*)d_in[0];
    const float* img2 = (const float*)d_in[1];

    k_init<<<1, 32>>>();
    k_pass1_main<<<2 * 96 * 96, 184>>>(img1, img2);
    k_pool_all<<<432, 256>>>();
    k_fuseA<<<NB2C(192) + NB1CUM(4), 128>>>();
    k_fuseB<<<NB3C(192) + NB2SCUM(4), 128>>>();
    k_fuseC<<<NB3SCUM(4), 128>>>();
    k_final<<<1, 1>>>((float*)d_out);
}